// round 7
// baseline (speedup 1.0000x reference)
#include <cuda_runtime.h>
#include <cstdint>

#define B 8
#define NPTS 2048
#define KNN 40
#define UMAXK 0xffffffffu

// ------------- static device scratch (no allocations) -------------
__device__ __align__(16) float g_xp0 [B*NPTS*16];   // layer-1 input, point-major, padded 9->16
__device__ __align__(16) float g_xcat[B*NPTS*128];  // x1..x4 point-major slices
__device__ __align__(16) float g_Z   [B*NPTS*32];
__device__ __align__(16) float g_T   [B*NPTS*32];
__device__ __align__(16) float g_Pmx [B*NPTS*32];
__device__ __align__(16) float g_Pmn [B*NPTS*32];
__device__ float g_xx[B*NPTS];
__device__ float g_stats[64];
__device__ float g_ss[64];

__device__ __forceinline__ unsigned fkey(float f) {
    unsigned u = __float_as_uint(f);
    return (u & 0x80000000u) ? ~u : (u | 0x80000000u);   // monotone float -> uint
}

// ------------- transpose + zero-pad x: (B,9,N) -> [b][n][16] -------------
__global__ void transpose_pad(const float* __restrict__ x)
{
    const int b = blockIdx.y;
    const int n = blockIdx.x * 256 + threadIdx.x;
    float* dst = g_xp0 + (size_t)(b*NPTS + n) * 16;
#pragma unroll
    for (int c = 0; c < 9; ++c) dst[c] = x[(size_t)(b*9 + c)*NPTS + n];
#pragma unroll
    for (int c = 9; c < 16; ++c) dst[c] = 0.f;
}

__global__ void zero_stats() { g_stats[threadIdx.x] = 0.f; }   // <<<1,64>>>

// ------------- Z = Wa*x, T = (Wb-Wa)*x, plus xx = ||x||^2 -------------
__global__ void __launch_bounds__(256) zt_kernel(int which, int xoff, int SP, int C,
                                                 const float* __restrict__ W)
{
    __shared__ float sx[8*32];
    __shared__ float sW[32*65];
    const int b  = blockIdx.y;
    const int n0 = blockIdx.x * 8;
    const int t  = threadIdx.x;
    const float* __restrict__ base = which ? (g_xcat + xoff) : g_xp0;

    for (int i = t; i < 32*64; i += 256) {
        int o = i >> 6, c = i & 63;
        sW[o*65 + c] = (c < 2*C) ? W[o*2*C + c] : 0.f;
    }
    {
        int p = t >> 5, c = t & 31;
        sx[p*32 + c] = (c < C) ? base[(size_t)(b*NPTS + n0 + p)*SP + c] : 0.f;
    }
    __syncthreads();

    const int p = t >> 5, o = t & 31;
    float z = 0.f, tt = 0.f;
    for (int c = 0; c < C; ++c) {
        float xv = sx[p*32 + c];
        z  = fmaf(sW[o*65 + c], xv, z);
        tt = fmaf(sW[o*65 + C + c] - sW[o*65 + c], xv, tt);
    }
    size_t idx = (size_t)(b*NPTS + n0 + p)*32 + o;
    g_Z[idx] = z;
    g_T[idx] = tt;

    if (t < 8) {    // xx with the same ascending fma chain as the knn dot (self-dist == 0 exactly)
        float xx = 0.f;
        for (int c = 0; c < C; ++c) { float v = sx[t*32 + c]; xx = fmaf(v, v, xx); }
        g_xx[b*NPTS + n0 + t] = xx;
    }
}

// ------------- fused knn + exact top-40 + Z-gather + BN-stat partials -------------
// 8 warps/block, warp = one query n; lane owns candidates m = slot*32 + lane.
template<int CP>
__global__ void __launch_bounds__(256) knn_main(int which, int xoff, int SP)
{
    constexpr int PAD = CP + 4;                 // pad-4 floats -> conflict-free LDS.128
    extern __shared__ unsigned char smraw[];
    float*    s_cand = (float*)smraw;                    // [256][PAD]
    float*    s_cxx  = s_cand + 256*PAD;                 // [256]
    unsigned* s_key  = (unsigned*)(s_cxx + 256);         // [8][2048]
    int*      s_idx  = (int*)(s_key + 8*2048);           // [8][KNN]
    float*    s_red  = (float*)(s_idx + 8*KNN);          // [512]

    const int b    = blockIdx.y;
    const int warp = threadIdx.x >> 5;
    const int lane = threadIdx.x & 31;
    const int n    = blockIdx.x * 8 + warp;
    const float* __restrict__ base = which ? (g_xcat + xoff) : g_xp0;

    float q[CP];
    {
        const float* qp = base + (size_t)(b*NPTS + n) * SP;
#pragma unroll
        for (int c = 0; c < CP; ++c) q[c] = qp[c];
    }
    const float xxq = g_xx[b*NPTS + n];

    // per-lane top-4 (key, slot), lexicographic (key asc, slot asc)
    unsigned ak0 = UMAXK, ak1 = UMAXK, ak2 = UMAXK, ak3 = UMAXK;
    int      as0 = 64,    as1 = 64,    as2 = 64,    as3 = 64;

    for (int tile = 0; tile < 8; ++tile) {
        __syncthreads();
        {   // cooperative stage: thread t stages candidate (tile*256 + t)
            const float* src = base + (size_t)(b*NPTS + tile*256 + threadIdx.x) * SP;
            float* dst = s_cand + threadIdx.x * PAD;
#pragma unroll
            for (int c4 = 0; c4 < CP; c4 += 4) {
                float4 v = *(const float4*)(src + c4);
                dst[c4+0] = v.x; dst[c4+1] = v.y; dst[c4+2] = v.z; dst[c4+3] = v.w;
            }
            s_cxx[threadIdx.x] = g_xx[b*NPTS + tile*256 + threadIdx.x];
        }
        __syncthreads();
#pragma unroll
        for (int j = 0; j < 8; ++j) {
            const int mm = j*32 + lane;
            const float4* cp4 = (const float4*)(s_cand + mm*PAD);
            float dot = 0.f;
#pragma unroll
            for (int c4 = 0; c4 < CP/4; ++c4) {
                float4 v = cp4[c4];
                dot = fmaf(v.x, q[c4*4+0], dot);
                dot = fmaf(v.y, q[c4*4+1], dot);
                dot = fmaf(v.z, q[c4*4+2], dot);
                dot = fmaf(v.w, q[c4*4+3], dot);
            }
            // reference order: (xx_n - 2*inner) + xx_m ; self-dist == +0 exactly
            float d = __fadd_rn(__fsub_rn(xxq, __fmul_rn(2.f, dot)), s_cxx[mm]);
            unsigned key = fkey(d);
            int slot = tile*8 + j;
            s_key[warp*2048 + slot*32 + lane] = key;
            if (key < ak3) {
                if (key < ak1) {
                    if (key < ak0) { ak3=ak2;as3=as2; ak2=ak1;as2=as1; ak1=ak0;as1=as0; ak0=key;as0=slot; }
                    else           { ak3=ak2;as3=as2; ak2=ak1;as2=as1; ak1=key;as1=slot; }
                } else {
                    if (key < ak2) { ak3=ak2;as3=as2; ak2=key;as2=slot; }
                    else           { ak3=key;as3=slot; }
                }
            }
        }
    }

    // ---- exact top-40 via REDUX pops; ties broken by min global index ----
    unsigned lastk = 0; int lasts = -1;
    for (int k = 0; k < KNN; ++k) {
        unsigned kmin = __reduce_min_sync(0xffffffffu, ak0);
        unsigned prop = (ak0 == kmin) ? (unsigned)((as0 << 5) | lane) : UMAXK;
        unsigned jsel = __reduce_min_sync(0xffffffffu, prop);
        if (prop == jsel) {                          // unique winner lane
            s_idx[warp*KNN + k] = (int)jsel;         // jsel == global point index
            lastk = ak0; lasts = as0;
            ak0 = ak1; as0 = as1; ak1 = ak2; as1 = as2; ak2 = ak3; as2 = as3;
            ak3 = UMAXK; as3 = 64;
            if (ak0 == UMAXK) {
                // lazy rescan: top-4 of this lane's keys strictly after (lastk, lasts)
                unsigned bk0=UMAXK,bk1=UMAXK,bk2=UMAXK,bk3=UMAXK;
                int      bs0=64,   bs1=64,   bs2=64,   bs3=64;
                for (int s = 0; s < 64; ++s) {
                    unsigned kk = s_key[warp*2048 + s*32 + lane];
                    if (kk > lastk || (kk == lastk && s > lasts)) {
                        if (kk < bk3) {
                            if (kk < bk1) {
                                if (kk < bk0) { bk3=bk2;bs3=bs2; bk2=bk1;bs2=bs1; bk1=bk0;bs1=bs0; bk0=kk;bs0=s; }
                                else          { bk3=bk2;bs3=bs2; bk2=bk1;bs2=bs1; bk1=kk;bs1=s; }
                            } else {
                                if (kk < bk2) { bk3=bk2;bs3=bs2; bk2=kk;bs2=s; }
                                else          { bk3=kk;bs3=s; }
                            }
                        }
                    }
                }
                ak0=bk0;as0=bs0; ak1=bk1;as1=bs1; ak2=bk2;as2=bs2; ak3=bk3;as3=bs3;
            }
        }
    }
    __syncwarp();

    // ---- gather neighbor Z rows (128B coalesced), per-channel partials ----
    float S1 = 0.f, S2 = 0.f, Mx = -3.4028235e38f, Mn = 3.4028235e38f;
    const float* Zb = g_Z + (size_t)b * NPTS * 32;
#pragma unroll 5
    for (int k = 0; k < KNN; ++k) {
        int j = s_idx[warp*KNN + k];
        float z = Zb[(size_t)j*32 + lane];
        S1 += z;
        S2 = fmaf(z, z, S2);
        Mx = fmaxf(Mx, z);
        Mn = fminf(Mn, z);
    }
    const size_t pi = (size_t)(b*NPTS + n)*32 + lane;
    const float t = g_T[pi];
    g_Pmx[pi] = Mx + t;
    g_Pmn[pi] = Mn + t;
    float ssum = S1 + (float)KNN * t;
    float qsum = S2 + 2.f*t*S1 + (float)KNN * t * t;

    s_red[warp*32 + lane]       = ssum;
    s_red[256 + warp*32 + lane] = qsum;
    __syncthreads();
    if (warp == 0) {
        float a = 0.f, c = 0.f;
#pragma unroll
        for (int w = 0; w < 8; ++w) { a += s_red[w*32 + lane]; c += s_red[256 + w*32 + lane]; }
        atomicAdd(&g_stats[lane],      a);
        atomicAdd(&g_stats[32 + lane], c);
    }
}

// ------------- finalize BN: scale/shift per channel -------------
__global__ void finalize_stats(const float* __restrict__ gamma, const float* __restrict__ beta)
{
    int o = threadIdx.x;                       // <<<1,32>>>
    const float cnt = (float)B * (float)NPTS * (float)KNN;
    float mean = g_stats[o] / cnt;
    float var  = g_stats[32 + o] / cnt - mean * mean;
    float inv  = rsqrtf(var + 1e-5f);
    float sc = gamma[o] * inv;
    g_ss[o]      = sc;
    g_ss[32 + o] = beta[o] - mean * sc;
}

// ------------- affine + leakyrelu on pre-max (monotone commute) + residual -------------
__global__ void __launch_bounds__(256) pass_d(int layer)
{
    const int b = blockIdx.y;
    const int n = blockIdx.x * 8 + (threadIdx.x >> 5);
    const int o = threadIdx.x & 31;
    size_t pi = (size_t)(b*NPTS + n)*32 + o;
    float sc = g_ss[o], sh = g_ss[32 + o];
    float pre = (sc >= 0.f) ? g_Pmx[pi] : g_Pmn[pi];
    float y = fmaf(pre, sc, sh);
    y = (y >= 0.f) ? y : 0.2f * y;
    size_t ci = (size_t)(b*NPTS + n) * 128;
    if (layer > 1) y += g_xcat[ci + 32*(layer - 2) + o];
    g_xcat[ci + 32*(layer - 1) + o] = y;
}

// ------------- out[b,o,n] = sum_c W5[o,c] * cat[b,c,n] -------------
__global__ void __launch_bounds__(128) final_gemm(const float* __restrict__ W5,
                                                  float* __restrict__ out)
{
    __shared__ float s[32*128];
    const int b = blockIdx.y, n0 = blockIdx.x * 32, t = threadIdx.x;
    const float* src = g_xcat + (size_t)(b*NPTS + n0) * 128;
    for (int i = t; i < 32*128/4; i += 128)
        ((float4*)s)[i] = ((const float4*)src)[i];
    __syncthreads();

    float acc[32];
#pragma unroll
    for (int n = 0; n < 32; ++n) acc[n] = 0.f;
    const float4* Wrow = (const float4*)(W5 + (size_t)t * 128);
#pragma unroll 8
    for (int c4 = 0; c4 < 32; ++c4) {
        float4 w = __ldg(Wrow + c4);
#pragma unroll
        for (int n = 0; n < 32; ++n) {
            float4 xv = ((const float4*)s)[n*32 + c4];
            acc[n] = fmaf(w.x, xv.x, acc[n]);
            acc[n] = fmaf(w.y, xv.y, acc[n]);
            acc[n] = fmaf(w.z, xv.z, acc[n]);
            acc[n] = fmaf(w.w, xv.w, acc[n]);
        }
    }
    __syncthreads();
#pragma unroll
    for (int n = 0; n < 32; ++n) s[t*32 + n] = acc[n];   // s becomes [128 o][32 n]
    __syncthreads();
    for (int i = t; i < 128*32; i += 128) {
        int o = i >> 5, n = i & 31;
        out[(size_t)(b*128 + o)*NPTS + n0 + n] = s[o*32 + n];
    }
}

// ------------------------------- host -------------------------------
static const int SMEM16 = 256*20*4 + 256*4 + 8*2048*4 + 8*KNN*4 + 512*4;   //  90368
static const int SMEM32 = 256*36*4 + 256*4 + 8*2048*4 + 8*KNN*4 + 512*4;   // 106752

extern "C" void kernel_launch(void* const* d_in, const int* in_sizes, int n_in,
                              void* d_out, int out_size)
{
    const float* x  = (const float*)d_in[0];
    const float* W1 = (const float*)d_in[1];
    const float* W2 = (const float*)d_in[2];
    const float* W3 = (const float*)d_in[3];
    const float* W4 = (const float*)d_in[4];
    const float* W5 = (const float*)d_in[5];
    const float* g1 = (const float*)d_in[6],  *b1 = (const float*)d_in[7];
    const float* g2 = (const float*)d_in[8],  *b2 = (const float*)d_in[9];
    const float* g3 = (const float*)d_in[10], *b3 = (const float*)d_in[11];
    const float* g4 = (const float*)d_in[12], *b4 = (const float*)d_in[13];
    float* out = (float*)d_out;

    cudaFuncSetAttribute(knn_main<16>, cudaFuncAttributeMaxDynamicSharedMemorySize, SMEM16);
    cudaFuncSetAttribute(knn_main<32>, cudaFuncAttributeMaxDynamicSharedMemorySize, SMEM32);

    dim3 g8(NPTS/8, B);
    dim3 gT(NPTS/256, B);

    transpose_pad<<<gT, 256>>>(x);

    // layer 1 (input: padded x, C=9, SP=16)
    zt_kernel<<<g8, 256>>>(0, 0, 16, 9, W1);
    zero_stats<<<1, 64>>>();
    knn_main<16><<<g8, 256, SMEM16>>>(0, 0, 16);
    finalize_stats<<<1, 32>>>(g1, b1);
    pass_d<<<g8, 256>>>(1);

    // layer 2 (input: x1 = slice 0, C=32, SP=128)
    zt_kernel<<<g8, 256>>>(1, 0, 128, 32, W2);
    zero_stats<<<1, 64>>>();
    knn_main<32><<<g8, 256, SMEM32>>>(1, 0, 128);
    finalize_stats<<<1, 32>>>(g2, b2);
    pass_d<<<g8, 256>>>(2);

    // layer 3 (input: x2 = slice 1)
    zt_kernel<<<g8, 256>>>(1, 32, 128, 32, W3);
    zero_stats<<<1, 64>>>();
    knn_main<32><<<g8, 256, SMEM32>>>(1, 32, 128);
    finalize_stats<<<1, 32>>>(g3, b3);
    pass_d<<<g8, 256>>>(3);

    // layer 4 (input: x3 = slice 2)
    zt_kernel<<<g8, 256>>>(1, 64, 128, 32, W4);
    zero_stats<<<1, 64>>>();
    knn_main<32><<<g8, 256, SMEM32>>>(1, 64, 128);
    finalize_stats<<<1, 32>>>(g4, b4);
    pass_d<<<g8, 256>>>(4);

    final_gemm<<<dim3(NPTS/32, B), 128>>>(W5, out);
}

// round 8
// speedup vs baseline: 1.1427x; 1.1427x over previous
#include <cuda_runtime.h>
#include <cstdint>

#define B 8
#define NPTS 2048
#define KNN 40
#define UMAXK 0xffffffffu

// ------------- static device scratch (no allocations) -------------
__device__ __align__(16) float g_xp0 [B*NPTS*12];   // layer-1 input, point-major, padded 9->12
__device__ __align__(16) float g_xcat[B*NPTS*128];  // x1..x4 point-major slices
__device__ __align__(16) float g_Z   [B*NPTS*32];
__device__ __align__(16) float g_T   [B*NPTS*32];
__device__ __align__(16) float g_Pmx [B*NPTS*32];
__device__ __align__(16) float g_Pmn [B*NPTS*32];
__device__ float g_xx[B*NPTS];
__device__ float g_stats[64];

__device__ __forceinline__ unsigned fkey(float f) {
    unsigned u = __float_as_uint(f);
    return (u & 0x80000000u) ? ~u : (u | 0x80000000u);   // monotone float -> uint
}

// ------------- transpose + zero-pad x: (B,9,N) -> [b][n][12] -------------
__global__ void transpose_pad(const float* __restrict__ x)
{
    const int b = blockIdx.y;
    const int n = blockIdx.x * 256 + threadIdx.x;
    float* dst = g_xp0 + (size_t)(b*NPTS + n) * 12;
#pragma unroll
    for (int c = 0; c < 9; ++c) dst[c] = x[(size_t)(b*9 + c)*NPTS + n];
    dst[9] = 0.f; dst[10] = 0.f; dst[11] = 0.f;
}

// ------------- Z = Wa*x, T = (Wb-Wa)*x, plus xx = ||x||^2; also zeroes stats -------------
__global__ void __launch_bounds__(256) zt_kernel(int which, int xoff, int SP, int C,
                                                 const float* __restrict__ W)
{
    __shared__ float sx[8*32];
    __shared__ float sW[32*65];
    const int b  = blockIdx.y;
    const int n0 = blockIdx.x * 8;
    const int t  = threadIdx.x;
    const float* __restrict__ base = which ? (g_xcat + xoff) : g_xp0;

    if (blockIdx.x == 0 && b == 0 && t < 64) g_stats[t] = 0.f;   // zero BN accumulators

    for (int i = t; i < 32*64; i += 256) {
        int o = i >> 6, c = i & 63;
        sW[o*65 + c] = (c < 2*C) ? W[o*2*C + c] : 0.f;
    }
    {
        int p = t >> 5, c = t & 31;
        sx[p*32 + c] = (c < C) ? base[(size_t)(b*NPTS + n0 + p)*SP + c] : 0.f;
    }
    __syncthreads();

    const int p = t >> 5, o = t & 31;
    float z = 0.f, tt = 0.f;
    for (int c = 0; c < C; ++c) {
        float xv = sx[p*32 + c];
        z  = fmaf(sW[o*65 + c], xv, z);
        tt = fmaf(sW[o*65 + C + c] - sW[o*65 + c], xv, tt);
    }
    size_t idx = (size_t)(b*NPTS + n0 + p)*32 + o;
    g_Z[idx] = z;
    g_T[idx] = tt;

    if (t < 8) {    // xx with the same ascending fma chain as the knn dot
        float xx = 0.f;
        for (int c = 0; c < C; ++c) { float v = sx[t*32 + c]; xx = fmaf(v, v, xx); }
        g_xx[b*NPTS + n0 + t] = xx;
    }
}

// ------------- fused knn + exact top-40 + Z-gather + BN-stat partials -------------
// 8 warps/block, warp = one query n; lane owns candidates m = slot*32 + lane.
// Per-lane register top-6 buffer; exhaustion (ultra-rare) triggers a deterministic
// recompute-rescan from global memory with identical rounding order.
template<int CP>
__global__ void __launch_bounds__(256, 4) knn_main(int which, int xoff, int SP)
{
    constexpr int STR = ((CP/4) & 1) ? CP : (CP + 4);   // odd # of float4 -> conflict-free
    extern __shared__ unsigned char smraw[];
    float* s_cand = (float*)smraw;                       // [256][STR]
    float* s_cxx  = s_cand + 256*STR;                    // [256]
    float* s_red  = s_cxx + 256;                         // [512]
    int*   s_idx  = (int*)(s_red + 512);                 // [8][KNN]

    const int b    = blockIdx.y;
    const int warp = threadIdx.x >> 5;
    const int lane = threadIdx.x & 31;
    const int n    = blockIdx.x * 8 + warp;
    const float* __restrict__ base = which ? (g_xcat + xoff) : g_xp0;

    float q[CP];
    {
        const float* qp = base + (size_t)(b*NPTS + n) * SP;
#pragma unroll
        for (int c = 0; c < CP; ++c) q[c] = qp[c];
    }
    const float xxq = g_xx[b*NPTS + n];

    // per-lane top-6 (key, slot), lexicographic (key asc, slot asc)
    unsigned k0=UMAXK,k1=UMAXK,k2=UMAXK,k3=UMAXK,k4=UMAXK,k5=UMAXK;
    int      s0=64,   s1=64,   s2=64,   s3=64,   s4=64,   s5=64;

    auto ins6 = [&](unsigned key, int slot) {
        if (key < k5) {
            if (key < k2) {
                if (key < k1) {
                    if (key < k0) { k5=k4;s5=s4; k4=k3;s4=s3; k3=k2;s3=s2; k2=k1;s2=s1; k1=k0;s1=s0; k0=key;s0=slot; }
                    else          { k5=k4;s5=s4; k4=k3;s4=s3; k3=k2;s3=s2; k2=k1;s2=s1; k1=key;s1=slot; }
                } else            { k5=k4;s5=s4; k4=k3;s4=s3; k3=k2;s3=s2; k2=key;s2=slot; }
            } else {
                if (key < k4) {
                    if (key < k3) { k5=k4;s5=s4; k4=k3;s4=s3; k3=key;s3=slot; }
                    else          { k5=k4;s5=s4; k4=key;s4=slot; }
                } else            { k5=key;s5=slot; }
            }
        }
    };

    for (int tile = 0; tile < 8; ++tile) {
        __syncthreads();
        {   // cooperative stage: thread t stages candidate (tile*256 + t), STS.128
            const float4* src = (const float4*)(base + (size_t)(b*NPTS + tile*256 + threadIdx.x) * SP);
            float4* dst = (float4*)(s_cand + threadIdx.x * STR);
#pragma unroll
            for (int c4 = 0; c4 < CP/4; ++c4) dst[c4] = src[c4];
            s_cxx[threadIdx.x] = g_xx[b*NPTS + tile*256 + threadIdx.x];
        }
        __syncthreads();
#pragma unroll
        for (int j = 0; j < 8; ++j) {
            const int mm = j*32 + lane;
            const float4* cp4 = (const float4*)(s_cand + mm*STR);
            float dot = 0.f;
#pragma unroll
            for (int c4 = 0; c4 < CP/4; ++c4) {
                float4 v = cp4[c4];
                dot = fmaf(v.x, q[c4*4+0], dot);
                dot = fmaf(v.y, q[c4*4+1], dot);
                dot = fmaf(v.z, q[c4*4+2], dot);
                dot = fmaf(v.w, q[c4*4+3], dot);
            }
            // reference order: (xx_n - 2*inner) + xx_m
            float d = __fadd_rn(__fsub_rn(xxq, __fmul_rn(2.f, dot)), s_cxx[mm]);
            ins6(fkey(d), tile*8 + j);
        }
    }

    // ---- exact top-40 via REDUX pops; ties broken by min global index ----
    unsigned lastk = 0; int lasts = -1;
    for (int k = 0; k < KNN; ++k) {
        unsigned kmin = __reduce_min_sync(0xffffffffu, k0);
        unsigned prop = (k0 == kmin) ? (unsigned)((s0 << 5) | lane) : UMAXK;
        unsigned jsel = __reduce_min_sync(0xffffffffu, prop);
        if (prop == jsel) {                          // unique winner lane
            s_idx[warp*KNN + k] = (int)jsel;         // jsel == global point index
            lastk = k0; lasts = s0;
            k0=k1;s0=s1; k1=k2;s1=s2; k2=k3;s2=s3; k3=k4;s3=s4; k4=k5;s4=s5;
            k5=UMAXK; s5=64;
            if (k0 == UMAXK) {
                // ultra-rare: deterministic recompute-rescan from global, keys
                // strictly after (lastk, lasts)
                for (int s = 0; s < 64; ++s) {
                    const int m = s*32 + lane;
                    const float4* cp4 = (const float4*)(base + (size_t)(b*NPTS + m) * SP);
                    float dot = 0.f;
#pragma unroll
                    for (int c4 = 0; c4 < CP/4; ++c4) {
                        float4 v = cp4[c4];
                        dot = fmaf(v.x, q[c4*4+0], dot);
                        dot = fmaf(v.y, q[c4*4+1], dot);
                        dot = fmaf(v.z, q[c4*4+2], dot);
                        dot = fmaf(v.w, q[c4*4+3], dot);
                    }
                    float d = __fadd_rn(__fsub_rn(xxq, __fmul_rn(2.f, dot)), g_xx[b*NPTS + m]);
                    unsigned kk = fkey(d);
                    if (kk > lastk || (kk == lastk && s > lasts)) ins6(kk, s);
                }
            }
        }
    }
    __syncwarp();

    // ---- gather neighbor Z rows (128B coalesced), per-channel partials ----
    float S1 = 0.f, S2 = 0.f, Mx = -3.4028235e38f, Mn = 3.4028235e38f;
    const float* Zb = g_Z + (size_t)b * NPTS * 32;
#pragma unroll 5
    for (int k = 0; k < KNN; ++k) {
        int j = s_idx[warp*KNN + k];
        float z = Zb[(size_t)j*32 + lane];
        S1 += z;
        S2 = fmaf(z, z, S2);
        Mx = fmaxf(Mx, z);
        Mn = fminf(Mn, z);
    }
    const size_t pi = (size_t)(b*NPTS + n)*32 + lane;
    const float t = g_T[pi];
    g_Pmx[pi] = Mx + t;
    g_Pmn[pi] = Mn + t;
    float ssum = S1 + (float)KNN * t;
    float qsum = S2 + 2.f*t*S1 + (float)KNN * t * t;

    s_red[warp*32 + lane]       = ssum;
    s_red[256 + warp*32 + lane] = qsum;
    __syncthreads();
    if (warp == 0) {
        float a = 0.f, c = 0.f;
#pragma unroll
        for (int w = 0; w < 8; ++w) { a += s_red[w*32 + lane]; c += s_red[256 + w*32 + lane]; }
        atomicAdd(&g_stats[lane],      a);
        atomicAdd(&g_stats[32 + lane], c);
    }
}

// ------------- BN finalize (redundant per thread) + affine + leakyrelu on pre-max + residual -------------
__global__ void __launch_bounds__(256) pass_d(int layer, const float* __restrict__ gamma,
                                              const float* __restrict__ beta)
{
    const int b = blockIdx.y;
    const int n = blockIdx.x * 8 + (threadIdx.x >> 5);
    const int o = threadIdx.x & 31;

    const float cnt = (float)B * (float)NPTS * (float)KNN;
    float mean = g_stats[o] / cnt;
    float var  = g_stats[32 + o] / cnt - mean * mean;
    float inv  = rsqrtf(var + 1e-5f);
    float sc = gamma[o] * inv;
    float sh = beta[o] - mean * sc;

    size_t pi = (size_t)(b*NPTS + n)*32 + o;
    float pre = (sc >= 0.f) ? g_Pmx[pi] : g_Pmn[pi];   // max commutes through monotone map
    float y = fmaf(pre, sc, sh);
    y = (y >= 0.f) ? y : 0.2f * y;
    size_t ci = (size_t)(b*NPTS + n) * 128;
    if (layer > 1) y += g_xcat[ci + 32*(layer - 2) + o];
    g_xcat[ci + 32*(layer - 1) + o] = y;
}

// ------------- out[b,o,n] = sum_c W5[o,c] * cat[b,c,n] -------------
__global__ void __launch_bounds__(128) final_gemm(const float* __restrict__ W5,
                                                  float* __restrict__ out)
{
    __shared__ float s[32*128];
    const int b = blockIdx.y, n0 = blockIdx.x * 32, t = threadIdx.x;
    const float* src = g_xcat + (size_t)(b*NPTS + n0) * 128;
    for (int i = t; i < 32*128/4; i += 128)
        ((float4*)s)[i] = ((const float4*)src)[i];
    __syncthreads();

    float acc[32];
#pragma unroll
    for (int n = 0; n < 32; ++n) acc[n] = 0.f;
    const float4* Wrow = (const float4*)(W5 + (size_t)t * 128);
#pragma unroll 8
    for (int c4 = 0; c4 < 32; ++c4) {
        float4 w = __ldg(Wrow + c4);
#pragma unroll
        for (int n = 0; n < 32; ++n) {
            float4 xv = ((const float4*)s)[n*32 + c4];
            acc[n] = fmaf(w.x, xv.x, acc[n]);
            acc[n] = fmaf(w.y, xv.y, acc[n]);
            acc[n] = fmaf(w.z, xv.z, acc[n]);
            acc[n] = fmaf(w.w, xv.w, acc[n]);
        }
    }
    __syncthreads();
#pragma unroll
    for (int n = 0; n < 32; ++n) s[t*32 + n] = acc[n];   // s becomes [128 o][32 n]
    __syncthreads();
    for (int i = t; i < 128*32; i += 128) {
        int o = i >> 5, n = i & 31;
        out[(size_t)(b*128 + o)*NPTS + n0 + n] = s[o*32 + n];
    }
}

// ------------------------------- host -------------------------------
static const int SMEM12 = (256*12 + 256 + 512)*4 + 8*KNN*4;   // 16640
static const int SMEM32 = (256*36 + 256 + 512)*4 + 8*KNN*4;   // 41216

extern "C" void kernel_launch(void* const* d_in, const int* in_sizes, int n_in,
                              void* d_out, int out_size)
{
    const float* x  = (const float*)d_in[0];
    const float* W1 = (const float*)d_in[1];
    const float* W2 = (const float*)d_in[2];
    const float* W3 = (const float*)d_in[3];
    const float* W4 = (const float*)d_in[4];
    const float* W5 = (const float*)d_in[5];
    const float* g1 = (const float*)d_in[6],  *b1 = (const float*)d_in[7];
    const float* g2 = (const float*)d_in[8],  *b2 = (const float*)d_in[9];
    const float* g3 = (const float*)d_in[10], *b3 = (const float*)d_in[11];
    const float* g4 = (const float*)d_in[12], *b4 = (const float*)d_in[13];
    float* out = (float*)d_out;

    cudaFuncSetAttribute(knn_main<12>, cudaFuncAttributeMaxDynamicSharedMemorySize, SMEM12);
    cudaFuncSetAttribute(knn_main<32>, cudaFuncAttributeMaxDynamicSharedMemorySize, SMEM32);

    dim3 g8(NPTS/8, B);
    dim3 gT(NPTS/256, B);

    transpose_pad<<<gT, 256>>>(x);

    // layer 1 (input: padded x, C=9, SP=12)
    zt_kernel<<<g8, 256>>>(0, 0, 12, 9, W1);
    knn_main<12><<<g8, 256, SMEM12>>>(0, 0, 12);
    pass_d<<<g8, 256>>>(1, g1, b1);

    // layer 2 (input: x1 = slice 0, C=32, SP=128)
    zt_kernel<<<g8, 256>>>(1, 0, 128, 32, W2);
    knn_main<32><<<g8, 256, SMEM32>>>(1, 0, 128);
    pass_d<<<g8, 256>>>(2, g2, b2);

    // layer 3 (input: x2 = slice 1)
    zt_kernel<<<g8, 256>>>(1, 32, 128, 32, W3);
    knn_main<32><<<g8, 256, SMEM32>>>(1, 32, 128);
    pass_d<<<g8, 256>>>(3, g3, b3);

    // layer 4 (input: x3 = slice 2)
    zt_kernel<<<g8, 256>>>(1, 64, 128, 32, W4);
    knn_main<32><<<g8, 256, SMEM32>>>(1, 64, 128);
    pass_d<<<g8, 256>>>(4, g4, b4);

    final_gemm<<<dim3(NPTS/32, B), 128>>>(W5, out);
}

// round 9
// speedup vs baseline: 1.9074x; 1.6693x over previous
#include <cuda_runtime.h>
#include <cstdint>

#define B 8
#define NPTS 2048
#define KNN 40
#define UMAXK 0xffffffffu

// ------------- static device scratch (no allocations) -------------
__device__ __align__(16) float g_xp0 [B*NPTS*12];   // layer-1 input, point-major, padded 9->12
__device__ __align__(16) float g_xcat[B*NPTS*128];  // x1..x4 point-major slices
__device__ __align__(16) float g_Z   [B*NPTS*32];
__device__ __align__(16) float g_T   [B*NPTS*32];
__device__ __align__(16) float g_Pmx [B*NPTS*32];
__device__ __align__(16) float g_Pmn [B*NPTS*32];
__device__ __align__(16) unsigned g_keys[(size_t)B*NPTS*NPTS];   // 134 MB dist keys
__device__ float  g_xx[B*NPTS];
__device__ double g_stats[64];

__device__ __forceinline__ unsigned fkey(float f) {
    unsigned u = __float_as_uint(f);
    return (u & 0x80000000u) ? ~u : (u | 0x80000000u);   // monotone float -> uint
}

// ------------- transpose + zero-pad x: (B,9,N) -> [b][n][12] -------------
__global__ void transpose_pad(const float* __restrict__ x)
{
    const int b = blockIdx.y;
    const int n = blockIdx.x * 256 + threadIdx.x;
    float* dst = g_xp0 + (size_t)(b*NPTS + n) * 12;
#pragma unroll
    for (int c = 0; c < 9; ++c) dst[c] = x[(size_t)(b*9 + c)*NPTS + n];
    dst[9] = 0.f; dst[10] = 0.f; dst[11] = 0.f;
}

// ------------- Z = Wa*x, T = (Wb-Wa)*x, plus xx = ||x||^2; also zeroes stats -------------
__global__ void __launch_bounds__(256) zt_kernel(int which, int xoff, int SP, int C,
                                                 const float* __restrict__ W)
{
    __shared__ float sx[8*32];
    __shared__ float sW[32*65];
    const int b  = blockIdx.y;
    const int n0 = blockIdx.x * 8;
    const int t  = threadIdx.x;
    const float* __restrict__ base = which ? (g_xcat + xoff) : g_xp0;

    if (blockIdx.x == 0 && b == 0 && t < 64) g_stats[t] = 0.0;   // zero BN accumulators

    for (int i = t; i < 32*64; i += 256) {
        int o = i >> 6, c = i & 63;
        sW[o*65 + c] = (c < 2*C) ? W[o*2*C + c] : 0.f;
    }
    {
        int p = t >> 5, c = t & 31;
        sx[p*32 + c] = (c < C) ? base[(size_t)(b*NPTS + n0 + p)*SP + c] : 0.f;
    }
    __syncthreads();

    const int p = t >> 5, o = t & 31;
    float z = 0.f, tt = 0.f;
    for (int c = 0; c < C; ++c) {
        float xv = sx[p*32 + c];
        z  = fmaf(sW[o*65 + c], xv, z);
        tt = fmaf(sW[o*65 + C + c] - sW[o*65 + c], xv, tt);
    }
    size_t idx = (size_t)(b*NPTS + n0 + p)*32 + o;
    g_Z[idx] = z;
    g_T[idx] = tt;

    if (t < 8) {    // xx with an ascending fma chain (matches gemm's dot order)
        float xx = 0.f;
        for (int c = 0; c < C; ++c) { float v = sx[t*32 + c]; xx = fmaf(v, v, xx); }
        g_xx[b*NPTS + n0 + t] = xx;
    }
}

// ------------- distance GEMM: keys[b][n][m] = fkey(xx_n - 2*dot(n,m) + xx_m) -------------
// block = 128 n x 128 m tile, 256 threads, 8x8 microtile per thread.
template<int C>
__global__ void __launch_bounds__(256) dist_gemm(int which, int xoff, int SP)
{
    __shared__ float Qs[C][128];
    __shared__ float Ms[C][128];
    const int b  = blockIdx.z;
    const int n0 = blockIdx.y * 128;
    const int m0 = blockIdx.x * 128;
    const float* __restrict__ base = which ? (g_xcat + xoff) : g_xp0;

    // stage tiles transposed ([c][point]); consecutive threads -> consecutive points
    for (int i = threadIdx.x; i < 128*(C/4); i += 256) {
        int c4 = i >> 7, p = i & 127;
        float4 vq = *(const float4*)(base + (size_t)(b*NPTS + n0 + p)*SP + c4*4);
        float4 vm = *(const float4*)(base + (size_t)(b*NPTS + m0 + p)*SP + c4*4);
        Qs[c4*4+0][p] = vq.x; Qs[c4*4+1][p] = vq.y; Qs[c4*4+2][p] = vq.z; Qs[c4*4+3][p] = vq.w;
        Ms[c4*4+0][p] = vm.x; Ms[c4*4+1][p] = vm.y; Ms[c4*4+2][p] = vm.z; Ms[c4*4+3][p] = vm.w;
    }
    __syncthreads();

    const int tx = threadIdx.x & 15;          // m direction
    const int ty = threadIdx.x >> 4;          // n direction
    float acc[8][8];
#pragma unroll
    for (int i = 0; i < 8; ++i)
#pragma unroll
        for (int j = 0; j < 8; ++j) acc[i][j] = 0.f;

#pragma unroll
    for (int c = 0; c < C; ++c) {
        float qf[8], mf[8];
        *(float4*)(qf)     = *(const float4*)&Qs[c][ty*8];
        *(float4*)(qf + 4) = *(const float4*)&Qs[c][ty*8 + 4];
        *(float4*)(mf)     = *(const float4*)&Ms[c][tx*8];
        *(float4*)(mf + 4) = *(const float4*)&Ms[c][tx*8 + 4];
#pragma unroll
        for (int i = 0; i < 8; ++i)
#pragma unroll
            for (int j = 0; j < 8; ++j)
                acc[i][j] = fmaf(qf[i], mf[j], acc[i][j]);
    }

    float xn[8], xm[8];
#pragma unroll
    for (int i = 0; i < 8; ++i) xn[i] = g_xx[b*NPTS + n0 + ty*8 + i];
#pragma unroll
    for (int j = 0; j < 8; ++j) xm[j] = g_xx[b*NPTS + m0 + tx*8 + j];

#pragma unroll
    for (int i = 0; i < 8; ++i) {
        unsigned kv[8];
#pragma unroll
        for (int j = 0; j < 8; ++j) {
            float d = __fadd_rn(__fsub_rn(xn[i], __fmul_rn(2.f, acc[i][j])), xm[j]);
            kv[j] = fkey(d);
        }
        unsigned* dst = g_keys + ((size_t)(b*NPTS + n0 + ty*8 + i))*NPTS + m0 + tx*8;
        *(uint4*)(dst)     = *(const uint4*)(kv);
        *(uint4*)(dst + 4) = *(const uint4*)(kv + 4);
    }
}

// ------------- selection + Z-gather + BN-stat partials -------------
// warp per query; lane owns m = s4*128 + lane*4 + e (16 x LDG.128, fully coalesced).
__global__ void __launch_bounds__(256) knn_sel(int b0)
{
    __shared__ int    s_idx[8*KNN];
    __shared__ double s_red[512];

    const int b    = blockIdx.y + b0;
    const int warp = threadIdx.x >> 5;
    const int lane = threadIdx.x & 31;
    const int n    = blockIdx.x * 8 + warp;

    const unsigned* __restrict__ keys = g_keys + ((size_t)(b*NPTS + n))*NPTS;

    // per-lane top-6 (key, m), lexicographic
    unsigned k0=UMAXK,k1=UMAXK,k2=UMAXK,k3=UMAXK,k4=UMAXK,k5=UMAXK;
    int      m0=NPTS, m1=NPTS, m2=NPTS, m3=NPTS, m4=NPTS, m5=NPTS;

    auto ins6 = [&](unsigned key, int m) {
        if (key < k5) {
            if (key < k2) {
                if (key < k1) {
                    if (key < k0) { k5=k4;m5=m4; k4=k3;m4=m3; k3=k2;m3=m2; k2=k1;m2=m1; k1=k0;m1=m0; k0=key;m0=m; }
                    else          { k5=k4;m5=m4; k4=k3;m4=m3; k3=k2;m3=m2; k2=k1;m2=m1; k1=key;m1=m; }
                } else            { k5=k4;m5=m4; k4=k3;m4=m3; k3=k2;m3=m2; k2=key;m2=m; }
            } else {
                if (key < k4) {
                    if (key < k3) { k5=k4;m5=m4; k4=k3;m4=m3; k3=key;m3=m; }
                    else          { k5=k4;m5=m4; k4=key;m4=m; }
                } else            { k5=key;m5=m; }
            }
        }
    };

#pragma unroll 4
    for (int s4 = 0; s4 < 16; ++s4) {
        const int mb = s4*128 + lane*4;
        uint4 kv = *(const uint4*)(keys + mb);
        ins6(kv.x, mb);
        ins6(kv.y, mb + 1);
        ins6(kv.z, mb + 2);
        ins6(kv.w, mb + 3);
    }

    // ---- exact top-40 via REDUX pops; ties broken by min global index ----
    unsigned lastk = 0; int lastm = -1;
    for (int k = 0; k < KNN; ++k) {
        unsigned kmin = __reduce_min_sync(0xffffffffu, k0);
        unsigned prop = (k0 == kmin) ? (unsigned)m0 : UMAXK;
        unsigned jsel = __reduce_min_sync(0xffffffffu, prop);
        if (prop == jsel) {                          // unique winner lane
            s_idx[warp*KNN + k] = (int)jsel;
            lastk = k0; lastm = m0;
            k0=k1;m0=m1; k1=k2;m1=m2; k2=k3;m2=m3; k3=k4;m3=m4; k4=k5;m4=m5;
            k5=UMAXK; m5=NPTS;
            if (k0 == UMAXK) {
                // rare: rescan this lane's stored keys strictly after (lastk, lastm)
                for (int s4 = 0; s4 < 16; ++s4) {
                    const int mb = s4*128 + lane*4;
                    uint4 kv = *(const uint4*)(keys + mb);
                    unsigned kk[4] = {kv.x, kv.y, kv.z, kv.w};
#pragma unroll
                    for (int e = 0; e < 4; ++e) {
                        int m = mb + e;
                        if (kk[e] > lastk || (kk[e] == lastk && m > lastm)) ins6(kk[e], m);
                    }
                }
            }
        }
    }
    __syncwarp();

    // ---- gather neighbor Z rows (128B coalesced), per-channel partials ----
    float S1 = 0.f, S2 = 0.f, Mx = -3.4028235e38f, Mn = 3.4028235e38f;
    const float* Zb = g_Z + (size_t)b * NPTS * 32;
#pragma unroll 5
    for (int k = 0; k < KNN; ++k) {
        int j = s_idx[warp*KNN + k];
        float z = Zb[(size_t)j*32 + lane];
        S1 += z;
        S2 = fmaf(z, z, S2);
        Mx = fmaxf(Mx, z);
        Mn = fminf(Mn, z);
    }
    const size_t pi = (size_t)(b*NPTS + n)*32 + lane;
    const float t = g_T[pi];
    g_Pmx[pi] = Mx + t;
    g_Pmn[pi] = Mn + t;
    double ssum = (double)S1 + (double)KNN * (double)t;
    double qsum = (double)S2 + 2.0*(double)t*(double)S1 + (double)KNN * (double)t * (double)t;

    s_red[warp*32 + lane]       = ssum;
    s_red[256 + warp*32 + lane] = qsum;
    __syncthreads();
    if (warp == 0) {
        double a = 0.0, c = 0.0;
#pragma unroll
        for (int w = 0; w < 8; ++w) { a += s_red[w*32 + lane]; c += s_red[256 + w*32 + lane]; }
        atomicAdd(&g_stats[lane],      a);
        atomicAdd(&g_stats[32 + lane], c);
    }
}

// ------------- BN finalize (redundant per thread) + affine + leakyrelu on pre-max + residual -------------
__global__ void __launch_bounds__(256) pass_d(int layer, const float* __restrict__ gamma,
                                              const float* __restrict__ beta)
{
    const int b = blockIdx.y;
    const int n = blockIdx.x * 8 + (threadIdx.x >> 5);
    const int o = threadIdx.x & 31;

    const double cnt = (double)B * (double)NPTS * (double)KNN;
    double meand = g_stats[o] / cnt;
    double vard  = g_stats[32 + o] / cnt - meand * meand;
    float mean = (float)meand;
    float var  = (float)vard;
    float inv  = rsqrtf(var + 1e-5f);
    float sc = gamma[o] * inv;
    float sh = beta[o] - mean * sc;

    size_t pi = (size_t)(b*NPTS + n)*32 + o;
    float pre = (sc >= 0.f) ? g_Pmx[pi] : g_Pmn[pi];   // max commutes through monotone map
    float y = fmaf(pre, sc, sh);
    y = (y >= 0.f) ? y : 0.2f * y;
    size_t ci = (size_t)(b*NPTS + n) * 128;
    if (layer > 1) y += g_xcat[ci + 32*(layer - 2) + o];
    g_xcat[ci + 32*(layer - 1) + o] = y;
}

// ------------- out[b,o,n] = sum_c W5[o,c] * cat[b,c,n] -------------
__global__ void __launch_bounds__(128) final_gemm(const float* __restrict__ W5,
                                                  float* __restrict__ out)
{
    __shared__ float s[32*128];
    const int b = blockIdx.y, n0 = blockIdx.x * 32, t = threadIdx.x;
    const float* src = g_xcat + (size_t)(b*NPTS + n0) * 128;
    for (int i = t; i < 32*128/4; i += 128)
        ((float4*)s)[i] = ((const float4*)src)[i];
    __syncthreads();

    float acc[32];
#pragma unroll
    for (int n = 0; n < 32; ++n) acc[n] = 0.f;
    const float4* Wrow = (const float4*)(W5 + (size_t)t * 128);
#pragma unroll 8
    for (int c4 = 0; c4 < 32; ++c4) {
        float4 w = __ldg(Wrow + c4);
#pragma unroll
        for (int n = 0; n < 32; ++n) {
            float4 xv = ((const float4*)s)[n*32 + c4];
            acc[n] = fmaf(w.x, xv.x, acc[n]);
            acc[n] = fmaf(w.y, xv.y, acc[n]);
            acc[n] = fmaf(w.z, xv.z, acc[n]);
            acc[n] = fmaf(w.w, xv.w, acc[n]);
        }
    }
    __syncthreads();
#pragma unroll
    for (int n = 0; n < 32; ++n) s[t*32 + n] = acc[n];   // s becomes [128 o][32 n]
    __syncthreads();
    for (int i = t; i < 128*32; i += 128) {
        int o = i >> 5, n = i & 31;
        out[(size_t)(b*128 + o)*NPTS + n0 + n] = s[o*32 + n];
    }
}

// ------------------------------- host -------------------------------
extern "C" void kernel_launch(void* const* d_in, const int* in_sizes, int n_in,
                              void* d_out, int out_size)
{
    const float* x  = (const float*)d_in[0];
    const float* W1 = (const float*)d_in[1];
    const float* W2 = (const float*)d_in[2];
    const float* W3 = (const float*)d_in[3];
    const float* W4 = (const float*)d_in[4];
    const float* W5 = (const float*)d_in[5];
    const float* g1 = (const float*)d_in[6],  *b1 = (const float*)d_in[7];
    const float* g2 = (const float*)d_in[8],  *b2 = (const float*)d_in[9];
    const float* g3 = (const float*)d_in[10], *b3 = (const float*)d_in[11];
    const float* g4 = (const float*)d_in[12], *b4 = (const float*)d_in[13];
    float* out = (float*)d_out;

    dim3 g8(NPTS/8, B);
    dim3 gT(NPTS/256, B);
    dim3 gG(NPTS/128, NPTS/128, B);

    transpose_pad<<<gT, 256>>>(x);

    // layer 1 (input: padded x, C=9 (pad 12), SP=12)
    zt_kernel<<<g8, 256>>>(0, 0, 12, 9, W1);
    dist_gemm<12><<<gG, 256>>>(0, 0, 12);
    knn_sel<<<g8, 256>>>(0);
    pass_d<<<g8, 256>>>(1, g1, b1);

    // layer 2 (input: x1 = slice 0, C=32, SP=128)
    zt_kernel<<<g8, 256>>>(1, 0, 128, 32, W2);
    dist_gemm<32><<<gG, 256>>>(1, 0, 128);
    knn_sel<<<g8, 256>>>(0);
    pass_d<<<g8, 256>>>(2, g2, b2);

    // layer 3 (input: x2 = slice 1)
    zt_kernel<<<g8, 256>>>(1, 32, 128, 32, W3);
    dist_gemm<32><<<gG, 256>>>(1, 32, 128);
    knn_sel<<<g8, 256>>>(0);
    pass_d<<<g8, 256>>>(3, g3, b3);

    // layer 4 (input: x3 = slice 2)
    zt_kernel<<<g8, 256>>>(1, 64, 128, 32, W4);
    dist_gemm<32><<<gG, 256>>>(1, 64, 128);
    knn_sel<<<g8, 256>>>(0);
    pass_d<<<g8, 256>>>(4, g4, b4);

    final_gemm<<<dim3(NPTS/32, B), 128>>>(W5, out);
}

// round 12
// speedup vs baseline: 2.4618x; 1.2907x over previous
#include <cuda_runtime.h>
#include <cstdint>

#define B 8
#define NPTS 2048
#define KNN 40
#define UMAXK 0xffffffffu
#define FULLM 0xffffffffu

// ------------- static device scratch (no allocations) -------------
__device__ __align__(16) float g_xp0 [B*NPTS*12];   // layer-1 input, point-major, padded 9->12
__device__ __align__(16) float g_xcat[B*NPTS*128];  // x1..x4 point-major slices
__device__ __align__(16) float g_Z   [B*NPTS*32];
__device__ __align__(16) float g_T   [B*NPTS*32];
__device__ __align__(16) float g_Pmx [B*NPTS*32];
__device__ __align__(16) float g_Pmn [B*NPTS*32];
__device__ __align__(16) unsigned g_keys[(size_t)B*NPTS*NPTS];   // 134 MB dist keys
__device__ float  g_xx[B*NPTS];
__device__ double g_stats[64];

__device__ __forceinline__ unsigned fkey(float f) {
    unsigned u = __float_as_uint(f);
    return (u & 0x80000000u) ? ~u : (u | 0x80000000u);   // monotone float -> uint
}

// packed f32x2 helpers (Blackwell): FFMA2 via PTX fma.rn.f32x2
__device__ __forceinline__ unsigned long long pk2(float lo, float hi) {
    unsigned long long r;
    asm("mov.b64 %0, {%1, %2};" : "=l"(r) : "f"(lo), "f"(hi));
    return r;
}
__device__ __forceinline__ void upk2(unsigned long long v, float& lo, float& hi) {
    asm("mov.b64 {%0, %1}, %2;" : "=f"(lo), "=f"(hi) : "l"(v));
}
__device__ __forceinline__ void ffma2(unsigned long long& d, unsigned long long a, unsigned long long b) {
    asm("fma.rn.f32x2 %0, %1, %2, %0;" : "+l"(d) : "l"(a), "l"(b));
}

// ------------- transpose + zero-pad x: (B,9,N) -> [b][n][12] -------------
__global__ void transpose_pad(const float* __restrict__ x)
{
    const int b = blockIdx.y;
    const int n = blockIdx.x * 256 + threadIdx.x;
    float* dst = g_xp0 + (size_t)(b*NPTS + n) * 12;
#pragma unroll
    for (int c = 0; c < 9; ++c) dst[c] = x[(size_t)(b*9 + c)*NPTS + n];
    dst[9] = 0.f; dst[10] = 0.f; dst[11] = 0.f;
}

// ------------- Z = Wa*x, T = (Wb-Wa)*x, plus xx = ||x||^2; also zeroes stats -------------
__global__ void __launch_bounds__(256) zt_kernel(int which, int xoff, int SP, int C,
                                                 const float* __restrict__ W)
{
    __shared__ float sx[8*32];
    __shared__ float sW[32*65];
    const int b  = blockIdx.y;
    const int n0 = blockIdx.x * 8;
    const int t  = threadIdx.x;
    const float* __restrict__ base = which ? (g_xcat + xoff) : g_xp0;

    if (blockIdx.x == 0 && b == 0 && t < 64) g_stats[t] = 0.0;   // zero BN accumulators

    for (int i = t; i < 32*64; i += 256) {
        int o = i >> 6, c = i & 63;
        sW[o*65 + c] = (c < 2*C) ? W[o*2*C + c] : 0.f;
    }
    {
        int p = t >> 5, c = t & 31;
        sx[p*32 + c] = (c < C) ? base[(size_t)(b*NPTS + n0 + p)*SP + c] : 0.f;
    }
    __syncthreads();

    const int p = t >> 5, o = t & 31;
    float z = 0.f, tt = 0.f;
    for (int c = 0; c < C; ++c) {
        float xv = sx[p*32 + c];
        z  = fmaf(sW[o*65 + c], xv, z);
        tt = fmaf(sW[o*65 + C + c] - sW[o*65 + c], xv, tt);
    }
    size_t idx = (size_t)(b*NPTS + n0 + p)*32 + o;
    g_Z[idx] = z;
    g_T[idx] = tt;

    if (t < 8) {    // xx with an ascending fma chain (matches gemm's dot order)
        float xx = 0.f;
        for (int c = 0; c < C; ++c) { float v = sx[t*32 + c]; xx = fmaf(v, v, xx); }
        g_xx[b*NPTS + n0 + t] = xx;
    }
}

// ------------- distance GEMM: keys[b][n][m] = fkey(xx_n - 2*dot(n,m) + xx_m) -------------
// block = 128 n x 128 m tile, 256 threads, 8x8 microtile per thread, FFMA2 packed over j.
template<int C>
__global__ void __launch_bounds__(256) dist_gemm(int which, int xoff, int SP)
{
    __shared__ float Qs[C][128];
    __shared__ float Ms[C][128];
    const int b  = blockIdx.z;
    const int n0 = blockIdx.y * 128;
    const int m0 = blockIdx.x * 128;
    const float* __restrict__ base = which ? (g_xcat + xoff) : g_xp0;

    // stage tiles transposed ([c][point]); consecutive threads -> consecutive points
    for (int i = threadIdx.x; i < 128*(C/4); i += 256) {
        int c4 = i >> 7, p = i & 127;
        float4 vq = *(const float4*)(base + (size_t)(b*NPTS + n0 + p)*SP + c4*4);
        float4 vm = *(const float4*)(base + (size_t)(b*NPTS + m0 + p)*SP + c4*4);
        Qs[c4*4+0][p] = vq.x; Qs[c4*4+1][p] = vq.y; Qs[c4*4+2][p] = vq.z; Qs[c4*4+3][p] = vq.w;
        Ms[c4*4+0][p] = vm.x; Ms[c4*4+1][p] = vm.y; Ms[c4*4+2][p] = vm.z; Ms[c4*4+3][p] = vm.w;
    }
    __syncthreads();

    const int tx = threadIdx.x & 15;          // m direction
    const int ty = threadIdx.x >> 4;          // n direction

    unsigned long long acc2[8][4];            // acc2[i][j2] = (acc[i][2j2], acc[i][2j2+1])
#pragma unroll
    for (int i = 0; i < 8; ++i)
#pragma unroll
        for (int j2 = 0; j2 < 4; ++j2) acc2[i][j2] = 0ull;

#pragma unroll
    for (int c = 0; c < C; ++c) {
        float qf[8], mf[8];
        *(float4*)(qf)     = *(const float4*)&Qs[c][ty*8];
        *(float4*)(qf + 4) = *(const float4*)&Qs[c][ty*8 + 4];
        *(float4*)(mf)     = *(const float4*)&Ms[c][tx*8];
        *(float4*)(mf + 4) = *(const float4*)&Ms[c][tx*8 + 4];
        unsigned long long mm[4];
#pragma unroll
        for (int j2 = 0; j2 < 4; ++j2) mm[j2] = pk2(mf[2*j2], mf[2*j2+1]);
#pragma unroll
        for (int i = 0; i < 8; ++i) {
            unsigned long long qq = pk2(qf[i], qf[i]);
#pragma unroll
            for (int j2 = 0; j2 < 4; ++j2) ffma2(acc2[i][j2], qq, mm[j2]);
        }
    }

    float xn[8], xm[8];
#pragma unroll
    for (int i = 0; i < 8; ++i) xn[i] = g_xx[b*NPTS + n0 + ty*8 + i];
#pragma unroll
    for (int j = 0; j < 8; ++j) xm[j] = g_xx[b*NPTS + m0 + tx*8 + j];

#pragma unroll
    for (int i = 0; i < 8; ++i) {
        float accr[8];
#pragma unroll
        for (int j2 = 0; j2 < 4; ++j2) upk2(acc2[i][j2], accr[2*j2], accr[2*j2+1]);
        unsigned kv[8];
#pragma unroll
        for (int j = 0; j < 8; ++j) {
            float d = __fadd_rn(__fsub_rn(xn[i], __fmul_rn(2.f, accr[j])), xm[j]);
            kv[j] = fkey(d);
        }
        unsigned* dst = g_keys + ((size_t)(b*NPTS + n0 + ty*8 + i))*NPTS + m0 + tx*8;
        *(uint4*)(dst)     = *(const uint4*)(kv);
        *(uint4*)(dst + 4) = *(const uint4*)(kv + 4);
    }
}

// ------------- selection: scan -> threshold -> collect -> trim; + Z-gather + BN partials -------------
// warp per query; lane owns m = s4*128 + lane*4 + e (16 x LDG.128, fully coalesced).
__global__ void __launch_bounds__(256) knn_sel()
{
    __shared__ unsigned long long s_list[8][128];
    __shared__ int    s_cnt[8];
    __shared__ int    s_idx[8*KNN];
    __shared__ double s_red[512];

    const int b    = blockIdx.y;
    const int warp = threadIdx.x >> 5;
    const int lane = threadIdx.x & 31;
    const int n    = blockIdx.x * 8 + warp;

    const unsigned* __restrict__ keys = g_keys + ((size_t)(b*NPTS + n))*NPTS;

    if (lane == 0) s_cnt[warp] = 0;
    __syncwarp();

    // ---- pass 1: branchless keys-only per-lane top-2 (3 IMNMX per key) ----
    unsigned k0 = UMAXK, k1 = UMAXK;
#pragma unroll 4
    for (int s4 = 0; s4 < 16; ++s4) {
        uint4 kv = *(const uint4*)(keys + s4*128 + lane*4);
        unsigned h;
        h = umax(kv.x, k0); k0 = umin(kv.x, k0); k1 = umin(h, k1);
        h = umax(kv.y, k0); k0 = umin(kv.y, k0); k1 = umin(h, k1);
        h = umax(kv.z, k0); k0 = umin(kv.z, k0); k1 = umin(h, k1);
        h = umax(kv.w, k0); k0 = umin(kv.w, k0); k1 = umin(h, k1);
    }

    // ---- threshold: exact 40th smallest of the 64 candidates (>= true 40th) ----
    unsigned T = 0;
    for (int k = 0; k < KNN; ++k) {
        T = __reduce_min_sync(FULLM, k0);
        unsigned bal = __ballot_sync(FULLM, k0 == T);
        if (lane == __ffs(bal) - 1) { k0 = k1; k1 = UMAXK; }
    }

    // ---- collect pass: all (key, m) with key <= T (expected ~44; L2-hot reread) ----
#pragma unroll 4
    for (int s4 = 0; s4 < 16; ++s4) {
        const int mb = s4*128 + lane*4;
        uint4 kv = *(const uint4*)(keys + mb);
        unsigned kk[4] = {kv.x, kv.y, kv.z, kv.w};
#pragma unroll
        for (int e = 0; e < 4; ++e) {
            if (kk[e] <= T) {
                int pos = atomicAdd(&s_cnt[warp], 1);
                if (pos < 128) s_list[warp][pos] = ((unsigned long long)kk[e] << 32) | (unsigned)(mb + e);
            }
        }
    }
    __syncwarp();
    const int Q = min(s_cnt[warp], 128);     // Q >= 40 guaranteed

    // ---- load candidates (lane owns lane+32r), sort 4 locally (lex = u64 order) ----
    unsigned long long c0 = (lane       < Q) ? s_list[warp][lane]      : ~0ull;
    unsigned long long c1 = (lane + 32  < Q) ? s_list[warp][lane + 32] : ~0ull;
    unsigned long long c2 = (lane + 64  < Q) ? s_list[warp][lane + 64] : ~0ull;
    unsigned long long c3 = (lane + 96  < Q) ? s_list[warp][lane + 96] : ~0ull;
    {
        unsigned long long t;
        if (c0 > c1) { t = c0; c0 = c1; c1 = t; }
        if (c2 > c3) { t = c2; c2 = c3; c3 = t; }
        if (c0 > c2) { t = c0; c0 = c2; c2 = t; }
        if (c1 > c3) { t = c1; c1 = c3; c3 = t; }
        if (c1 > c2) { t = c1; c1 = c2; c2 = t; }
    }

    // ---- trim: exact top-40 by (key, m) lex; ties -> smallest m (matches lax.top_k) ----
    for (int k = 0; k < KNN; ++k) {
        unsigned hi = (unsigned)(c0 >> 32);
        unsigned kmin = __reduce_min_sync(FULLM, hi);
        unsigned mprop = (hi == kmin) ? (unsigned)c0 : UMAXK;
        unsigned msel  = __reduce_min_sync(FULLM, mprop);
        if (hi == kmin && (unsigned)c0 == msel) { c0 = c1; c1 = c2; c2 = c3; c3 = ~0ull; }
        if (lane == 0) s_idx[warp*KNN + k] = (int)msel;
    }
    __syncwarp();

    // ---- gather neighbor Z rows (128B coalesced, high MLP), per-channel partials ----
    float S1 = 0.f, S2 = 0.f, Mx = -3.4028235e38f, Mn = 3.4028235e38f;
    const float* Zb = g_Z + (size_t)b * NPTS * 32;
#pragma unroll 5
    for (int k = 0; k < KNN; ++k) {
        int j = s_idx[warp*KNN + k];
        float z = Zb[(size_t)j*32 + lane];
        S1 += z;
        S2 = fmaf(z, z, S2);
        Mx = fmaxf(Mx, z);
        Mn = fminf(Mn, z);
    }
    const int nn = n;
    const size_t pi = (size_t)(b*NPTS + nn)*32 + lane;
    const float t = g_T[pi];
    g_Pmx[pi] = Mx + t;
    g_Pmn[pi] = Mn + t;
    double ssum = (double)S1 + (double)KNN * (double)t;
    double qsum = (double)S2 + 2.0*(double)t*(double)S1 + (double)KNN * (double)t * (double)t;

    s_red[warp*32 + lane]       = ssum;
    s_red[256 + warp*32 + lane] = qsum;
    __syncthreads();
    if (warp == 0) {
        double a = 0.0, c = 0.0;
#pragma unroll
        for (int w = 0; w < 8; ++w) { a += s_red[w*32 + lane]; c += s_red[256 + w*32 + lane]; }
        atomicAdd(&g_stats[lane],      a);
        atomicAdd(&g_stats[32 + lane], c);
    }
}

// ------------- BN finalize (redundant per thread) + affine + leakyrelu on pre-max + residual -------------
__global__ void __launch_bounds__(256) pass_d(int layer, const float* __restrict__ gamma,
                                              const float* __restrict__ beta)
{
    const int b = blockIdx.y;
    const int n = blockIdx.x * 8 + (threadIdx.x >> 5);
    const int o = threadIdx.x & 31;

    const double cnt = (double)B * (double)NPTS * (double)KNN;
    double meand = g_stats[o] / cnt;
    double vard  = g_stats[32 + o] / cnt - meand * meand;
    float mean = (float)meand;
    float var  = (float)vard;
    float inv  = rsqrtf(var + 1e-5f);
    float sc = gamma[o] * inv;
    float sh = beta[o] - mean * sc;

    size_t pi = (size_t)(b*NPTS + n)*32 + o;
    float pre = (sc >= 0.f) ? g_Pmx[pi] : g_Pmn[pi];   // max commutes through monotone map
    float y = fmaf(pre, sc, sh);
    y = (y >= 0.f) ? y : 0.2f * y;
    size_t ci = (size_t)(b*NPTS + n) * 128;
    if (layer > 1) y += g_xcat[ci + 32*(layer - 2) + o];
    g_xcat[ci + 32*(layer - 1) + o] = y;
}

// ------------- out[b,o,n] = sum_c W5[o,c] * cat[b,c,n] -------------
__global__ void __launch_bounds__(128) final_gemm(const float* __restrict__ W5,
                                                  float* __restrict__ out)
{
    __shared__ float s[32*128];
    const int b = blockIdx.y, n0 = blockIdx.x * 32, t = threadIdx.x;
    const float* src = g_xcat + (size_t)(b*NPTS + n0) * 128;
    for (int i = t; i < 32*128/4; i += 128)
        ((float4*)s)[i] = ((const float4*)src)[i];
    __syncthreads();

    float acc[32];
#pragma unroll
    for (int n = 0; n < 32; ++n) acc[n] = 0.f;
    const float4* Wrow = (const float4*)(W5 + (size_t)t * 128);
#pragma unroll 8
    for (int c4 = 0; c4 < 32; ++c4) {
        float4 w = __ldg(Wrow + c4);
#pragma unroll
        for (int n = 0; n < 32; ++n) {
            float4 xv = ((const float4*)s)[n*32 + c4];
            acc[n] = fmaf(w.x, xv.x, acc[n]);
            acc[n] = fmaf(w.y, xv.y, acc[n]);
            acc[n] = fmaf(w.z, xv.z, acc[n]);
            acc[n] = fmaf(w.w, xv.w, acc[n]);
        }
    }
    __syncthreads();
#pragma unroll
    for (int n = 0; n < 32; ++n) s[t*32 + n] = acc[n];   // s becomes [128 o][32 n]
    __syncthreads();
    for (int i = t; i < 128*32; i += 128) {
        int o = i >> 5, n = i & 31;
        out[(size_t)(b*128 + o)*NPTS + n0 + n] = s[o*32 + n];
    }
}

// ------------------------------- host -------------------------------
extern "C" void kernel_launch(void* const* d_in, const int* in_sizes, int n_in,
                              void* d_out, int out_size)
{
    const float* x  = (const float*)d_in[0];
    const float* W1 = (const float*)d_in[1];
    const float* W2 = (const float*)d_in[2];
    const float* W3 = (const float*)d_in[3];
    const float* W4 = (const float*)d_in[4];
    const float* W5 = (const float*)d_in[5];
    const float* g1 = (const float*)d_in[6],  *b1 = (const float*)d_in[7];
    const float* g2 = (const float*)d_in[8],  *b2 = (const float*)d_in[9];
    const float* g3 = (const float*)d_in[10], *b3 = (const float*)d_in[11];
    const float* g4 = (const float*)d_in[12], *b4 = (const float*)d_in[13];
    float* out = (float*)d_out;

    dim3 g8(NPTS/8, B);
    dim3 gT(NPTS/256, B);
    dim3 gG(NPTS/128, NPTS/128, B);

    transpose_pad<<<gT, 256>>>(x);

    // layer 1 (input: padded x, C=9 (pad 12), SP=12)
    zt_kernel<<<g8, 256>>>(0, 0, 12, 9, W1);
    dist_gemm<12><<<gG, 256>>>(0, 0, 12);
    knn_sel<<<g8, 256>>>();
    pass_d<<<g8, 256>>>(1, g1, b1);

    // layer 2 (input: x1 = slice 0, C=32, SP=128)
    zt_kernel<<<g8, 256>>>(1, 0, 128, 32, W2);
    dist_gemm<32><<<gG, 256>>>(1, 0, 128);
    knn_sel<<<g8, 256>>>();
    pass_d<<<g8, 256>>>(2, g2, b2);

    // layer 3 (input: x2 = slice 1)
    zt_kernel<<<g8, 256>>>(1, 32, 128, 32, W3);
    dist_gemm<32><<<gG, 256>>>(1, 32, 128);
    knn_sel<<<g8, 256>>>();
    pass_d<<<g8, 256>>>(3, g3, b3);

    // layer 4 (input: x3 = slice 2)
    zt_kernel<<<g8, 256>>>(1, 64, 128, 32, W4);
    dist_gemm<32><<<gG, 256>>>(1, 64, 128);
    knn_sel<<<g8, 256>>>();
    pass_d<<<g8, 256>>>(4, g4, b4);

    final_gemm<<<dim3(NPTS/32, B), 128>>>(W5, out);
}

// round 14
// speedup vs baseline: 2.5905x; 1.0523x over previous
#include <cuda_runtime.h>
#include <cstdint>

#define B 8
#define NPTS 2048
#define KNN 40
#define UMAXK 0xffffffffu
#define FULLM 0xffffffffu
#define CCAP 192

// ------------- static device scratch (no allocations) -------------
__device__ __align__(16) float g_xp0 [B*NPTS*12];   // layer-1 input, point-major, padded 9->12
__device__ __align__(16) float g_xcat[B*NPTS*128];  // x1..x4 point-major slices
__device__ __align__(16) float g_Z   [B*NPTS*32];
__device__ __align__(16) float g_T   [B*NPTS*32];
__device__ __align__(16) float g_Pmx [B*NPTS*32];
__device__ __align__(16) float g_Pmn [B*NPTS*32];
__device__ __align__(16) unsigned short g_keys16[(size_t)B*NPTS*NPTS];  // 67 MB truncated keys
__device__ float  g_xx[B*NPTS];
__device__ double g_stats[64];

__device__ __forceinline__ unsigned fkey(float f) {
    unsigned u = __float_as_uint(f);
    return (u & 0x80000000u) ? ~u : (u | 0x80000000u);   // monotone float -> uint
}

// packed f32x2 helpers (Blackwell): FFMA2 via PTX fma.rn.f32x2
__device__ __forceinline__ unsigned long long pk2(float lo, float hi) {
    unsigned long long r;
    asm("mov.b64 %0, {%1, %2};" : "=l"(r) : "f"(lo), "f"(hi));
    return r;
}
__device__ __forceinline__ void upk2(unsigned long long v, float& lo, float& hi) {
    asm("mov.b64 {%0, %1}, %2;" : "=f"(lo), "=f"(hi) : "l"(v));
}
__device__ __forceinline__ void ffma2(unsigned long long& d, unsigned long long a, unsigned long long b) {
    asm("fma.rn.f32x2 %0, %1, %2, %0;" : "+l"(d) : "l"(a), "l"(b));
}

// ------------- transpose + zero-pad x: (B,9,N) -> [b][n][12] -------------
__global__ void transpose_pad(const float* __restrict__ x)
{
    const int b = blockIdx.y;
    const int n = blockIdx.x * 256 + threadIdx.x;
    float* dst = g_xp0 + (size_t)(b*NPTS + n) * 12;
#pragma unroll
    for (int c = 0; c < 9; ++c) dst[c] = x[(size_t)(b*9 + c)*NPTS + n];
    dst[9] = 0.f; dst[10] = 0.f; dst[11] = 0.f;
}

// ------------- layer-1 ZT: Z = Wa*x, T = (Wb-Wa)*x, xx = ||x||^2 -------------
__global__ void __launch_bounds__(256) zt_first(const float* __restrict__ W)
{
    __shared__ float sx[8*32];
    __shared__ float sW[32*65];
    const int b  = blockIdx.y;
    const int n0 = blockIdx.x * 8;
    const int t  = threadIdx.x;
    const int C = 9, SP = 12;

    for (int i = t; i < 32*64; i += 256) {
        int o = i >> 6, c = i & 63;
        sW[o*65 + c] = (c < 2*C) ? W[o*2*C + c] : 0.f;
    }
    {
        int p = t >> 5, c = t & 31;
        sx[p*32 + c] = (c < C) ? g_xp0[(size_t)(b*NPTS + n0 + p)*SP + c] : 0.f;
    }
    __syncthreads();

    const int p = t >> 5, o = t & 31;
    float z = 0.f, tt = 0.f;
    for (int c = 0; c < C; ++c) {
        float xv = sx[p*32 + c];
        z  = fmaf(sW[o*65 + c], xv, z);
        tt = fmaf(sW[o*65 + C + c] - sW[o*65 + c], xv, tt);
    }
    size_t idx = (size_t)(b*NPTS + n0 + p)*32 + o;
    g_Z[idx] = z;
    g_T[idx] = tt;

    if (t < 8) {
        float xx = 0.f;
        for (int c = 0; c < C; ++c) { float v = sx[t*32 + c]; xx = fmaf(v, v, xx); }
        g_xx[b*NPTS + n0 + t] = xx;
    }
}

// ------------- fused: BN finalize + affine + leakyrelu + residual (prev layer) THEN ZT (next) -------------
__global__ void __launch_bounds__(256) zt_fused(int prevLayer, const float* __restrict__ gamma,
                                                const float* __restrict__ beta,
                                                const float* __restrict__ W)
{
    __shared__ float sx[8*32];
    __shared__ float sW[32*65];
    const int b  = blockIdx.y;
    const int n0 = blockIdx.x * 8;
    const int t  = threadIdx.x;
    const int p = t >> 5, o = t & 31;

    for (int i = t; i < 32*64; i += 256) {
        int oo = i >> 6, c = i & 63;
        sW[oo*65 + c] = W[oo*64 + c];
    }

    // ---- pass-d for prevLayer ----
    const double cnt = (double)B * (double)NPTS * (double)KNN;
    double meand = g_stats[o] / cnt;
    double vard  = g_stats[32 + o] / cnt - meand * meand;
    float inv  = rsqrtf((float)vard + 1e-5f);
    float sc = gamma[o] * inv;
    float sh = beta[o] - (float)meand * sc;

    size_t pi = (size_t)(b*NPTS + n0 + p)*32 + o;
    float pre = (sc >= 0.f) ? g_Pmx[pi] : g_Pmn[pi];   // max commutes through monotone map
    float y = fmaf(pre, sc, sh);
    y = (y >= 0.f) ? y : 0.2f * y;
    size_t ci = (size_t)(b*NPTS + n0 + p) * 128;
    if (prevLayer > 1) y += g_xcat[ci + 32*(prevLayer - 2) + o];
    g_xcat[ci + 32*(prevLayer - 1) + o] = y;
    sx[p*32 + o] = y;
    __syncthreads();

    // ---- ZT for layer prevLayer+1 (C=32) ----
    float z = 0.f, tt = 0.f;
    for (int c = 0; c < 32; ++c) {
        float xv = sx[p*32 + c];
        z  = fmaf(sW[o*65 + c], xv, z);
        tt = fmaf(sW[o*65 + 32 + c] - sW[o*65 + c], xv, tt);
    }
    g_Z[pi] = z;
    g_T[pi] = tt;

    if (t < 8) {
        float xx = 0.f;
        for (int c = 0; c < 32; ++c) { float v = sx[t*32 + c]; xx = fmaf(v, v, xx); }
        g_xx[b*NPTS + n0 + t] = xx;
    }
}

// ------------- distance GEMM -> truncated u16 keys; also zeroes BN stats -------------
// block = 128 n x 128 m tile, 256 threads, 8x8 microtile per thread, FFMA2 packed over j.
template<int C>
__global__ void __launch_bounds__(256) dist_gemm(int which, int xoff, int SP)
{
    __shared__ float Qs[C][128];
    __shared__ float Ms[C][128];
    const int b  = blockIdx.z;
    const int n0 = blockIdx.y * 128;
    const int m0 = blockIdx.x * 128;
    const float* __restrict__ base = which ? (g_xcat + xoff) : g_xp0;

    if (blockIdx.x == 0 && blockIdx.y == 0 && b == 0 && threadIdx.x < 64)
        g_stats[threadIdx.x] = 0.0;     // zero BN accumulators for this layer

    for (int i = threadIdx.x; i < 128*(C/4); i += 256) {
        int c4 = i >> 7, p = i & 127;
        float4 vq = *(const float4*)(base + (size_t)(b*NPTS + n0 + p)*SP + c4*4);
        float4 vm = *(const float4*)(base + (size_t)(b*NPTS + m0 + p)*SP + c4*4);
        Qs[c4*4+0][p] = vq.x; Qs[c4*4+1][p] = vq.y; Qs[c4*4+2][p] = vq.z; Qs[c4*4+3][p] = vq.w;
        Ms[c4*4+0][p] = vm.x; Ms[c4*4+1][p] = vm.y; Ms[c4*4+2][p] = vm.z; Ms[c4*4+3][p] = vm.w;
    }
    __syncthreads();

    const int tx = threadIdx.x & 15;          // m direction
    const int ty = threadIdx.x >> 4;          // n direction

    unsigned long long acc2[8][4];
#pragma unroll
    for (int i = 0; i < 8; ++i)
#pragma unroll
        for (int j2 = 0; j2 < 4; ++j2) acc2[i][j2] = 0ull;

#pragma unroll
    for (int c = 0; c < C; ++c) {
        float qf[8], mf[8];
        *(float4*)(qf)     = *(const float4*)&Qs[c][ty*8];
        *(float4*)(qf + 4) = *(const float4*)&Qs[c][ty*8 + 4];
        *(float4*)(mf)     = *(const float4*)&Ms[c][tx*8];
        *(float4*)(mf + 4) = *(const float4*)&Ms[c][tx*8 + 4];
        unsigned long long mm[4];
#pragma unroll
        for (int j2 = 0; j2 < 4; ++j2) mm[j2] = pk2(mf[2*j2], mf[2*j2+1]);
#pragma unroll
        for (int i = 0; i < 8; ++i) {
            unsigned long long qq = pk2(qf[i], qf[i]);
#pragma unroll
            for (int j2 = 0; j2 < 4; ++j2) ffma2(acc2[i][j2], qq, mm[j2]);
        }
    }

    float xn[8], xm[8];
#pragma unroll
    for (int i = 0; i < 8; ++i) xn[i] = g_xx[b*NPTS + n0 + ty*8 + i];
#pragma unroll
    for (int j = 0; j < 8; ++j) xm[j] = g_xx[b*NPTS + m0 + tx*8 + j];

#pragma unroll
    for (int i = 0; i < 8; ++i) {
        float accr[8];
#pragma unroll
        for (int j2 = 0; j2 < 4; ++j2) upk2(acc2[i][j2], accr[2*j2], accr[2*j2+1]);
        unsigned kv[8];
#pragma unroll
        for (int j = 0; j < 8; ++j) {
            float d = __fadd_rn(__fsub_rn(xn[i], __fmul_rn(2.f, accr[j])), xm[j]);
            kv[j] = fkey(d);
        }
        // pack upper halves: word = key16(lo) | key16(hi)<<16 via PRMT
        uint4 w;
        w.x = __byte_perm(kv[0], kv[1], 0x7632);
        w.y = __byte_perm(kv[2], kv[3], 0x7632);
        w.z = __byte_perm(kv[4], kv[5], 0x7632);
        w.w = __byte_perm(kv[6], kv[7], 0x7632);
        unsigned short* dst = g_keys16 + ((size_t)(b*NPTS + n0 + ty*8 + i))*NPTS + m0 + tx*8;
        *(uint4*)dst = w;
    }
}

// ------------- selection: u16 scan -> exact subset-rank-40 threshold -> collect -> recompute trim -------------
// warp per query; 8 u16x8 (uint4) loads per lane per pass, fully coalesced.
template<int CP>
__global__ void __launch_bounds__(256) knn_sel(int which, int xoff, int SP)
{
    __shared__ unsigned s_list[8][CCAP];
    __shared__ int    s_cnt[8];
    __shared__ int    s_idx[8*KNN];
    __shared__ double s_red[512];

    const int b    = blockIdx.y;
    const int warp = threadIdx.x >> 5;
    const int lane = threadIdx.x & 31;
    const int n    = blockIdx.x * 8 + warp;
    const float* __restrict__ base = which ? (g_xcat + xoff) : g_xp0;

    const uint4* __restrict__ krow4 =
        (const uint4*)(g_keys16 + ((size_t)(b*NPTS + n))*NPTS);

    if (lane == 0) s_cnt[warp] = 0;
    __syncwarp();

    // ---- pass 1: branchless per-lane top-2 of u16 keys ----
    unsigned k0 = UMAXK, k1 = UMAXK;
#pragma unroll
    for (int s = 0; s < 8; ++s) {
        uint4 kv = krow4[s*32 + lane];
        unsigned w[4] = {kv.x, kv.y, kv.z, kv.w};
#pragma unroll
        for (int wi = 0; wi < 4; ++wi) {
            unsigned lo = w[wi] & 0xffffu, hi = w[wi] >> 16, h;
            h = umax(lo, k0); k0 = umin(lo, k0); k1 = umin(h, k1);
            h = umax(hi, k0); k0 = umin(hi, k0); k1 = umin(h, k1);
        }
    }

    // ---- threshold: exact 40th smallest of the 64-candidate subset (>= row rank-40 key16,
    //      and >= key16 of every true top-40 element => collect is a superset) ----
    unsigned T = 0;
    for (int k = 0; k < KNN; ++k) {
        T = __reduce_min_sync(FULLM, k0);
        unsigned bal = __ballot_sync(FULLM, k0 == T);
        if (lane == (unsigned)(__ffs(bal) - 1)) { k0 = k1; k1 = UMAXK; }
    }

    // ---- collect: all m with key16 <= T (count ~= 40 + u16 ties << CCAP) ----
#pragma unroll
    for (int s = 0; s < 8; ++s) {
        uint4 kv = krow4[s*32 + lane];
        unsigned w[4] = {kv.x, kv.y, kv.z, kv.w};
        const int mb = (s*32 + lane)*8;
#pragma unroll
        for (int wi = 0; wi < 4; ++wi) {
            unsigned lo = w[wi] & 0xffffu, hi = w[wi] >> 16;
            if (lo <= T) { int pos = atomicAdd(&s_cnt[warp], 1); if (pos < CCAP) s_list[warp][pos] = mb + wi*2; }
            if (hi <= T) { int pos = atomicAdd(&s_cnt[warp], 1); if (pos < CCAP) s_list[warp][pos] = mb + wi*2 + 1; }
        }
    }
    __syncwarp();
    const int Q = min(s_cnt[warp], CCAP);

    // ---- recompute exact key32 per candidate (bit-identical chain to dist_gemm) ----
    float q[CP];
    {
        const float4* qp = (const float4*)(base + (size_t)(b*NPTS + n) * SP);
#pragma unroll
        for (int c4 = 0; c4 < CP/4; ++c4) *(float4*)(q + c4*4) = qp[c4];
    }
    const float xxq = g_xx[b*NPTS + n];

    unsigned long long cand[6];
#pragma unroll
    for (int r = 0; r < 6; ++r) {
        cand[r] = ~0ull;
        int idx = r*32 + lane;
        if (idx < Q) {
            int m = s_list[warp][idx];
            const float4* cp4 = (const float4*)(base + (size_t)(b*NPTS + m) * SP);
            float dot = 0.f;
#pragma unroll
            for (int c4 = 0; c4 < CP/4; ++c4) {
                float4 v = cp4[c4];
                dot = fmaf(v.x, q[c4*4+0], dot);
                dot = fmaf(v.y, q[c4*4+1], dot);
                dot = fmaf(v.z, q[c4*4+2], dot);
                dot = fmaf(v.w, q[c4*4+3], dot);
            }
            float d = __fadd_rn(__fsub_rn(xxq, __fmul_rn(2.f, dot)), g_xx[b*NPTS + m]);
            cand[r] = ((unsigned long long)fkey(d) << 32) | (unsigned)m;
        }
    }
    // sort 6 (Bose-Nelson 12-CE network); u64 order == (key, m) lex
    {
        unsigned long long t;
#define CE(a,bq) if (cand[a] > cand[bq]) { t = cand[a]; cand[a] = cand[bq]; cand[bq] = t; }
        CE(1,2) CE(4,5) CE(0,2) CE(3,5) CE(0,1) CE(3,4)
        CE(2,5) CE(0,3) CE(1,4) CE(2,4) CE(1,3) CE(2,3)
#undef CE
    }

    // ---- trim: exact top-40 by (key, m); ties -> smallest m (lax.top_k semantics) ----
    for (int k = 0; k < KNN; ++k) {
        unsigned hi = (unsigned)(cand[0] >> 32);
        unsigned kmin = __reduce_min_sync(FULLM, hi);
        unsigned mprop = (hi == kmin) ? (unsigned)cand[0] : UMAXK;
        unsigned msel  = __reduce_min_sync(FULLM, mprop);
        if (hi == kmin && (unsigned)cand[0] == msel) {
            cand[0]=cand[1]; cand[1]=cand[2]; cand[2]=cand[3]; cand[3]=cand[4]; cand[4]=cand[5];
            cand[5] = ~0ull;
        }
        if (lane == 0) s_idx[warp*KNN + k] = (int)msel;
    }
    __syncwarp();

    // ---- gather neighbor Z rows (128B coalesced), per-channel partials ----
    float S1 = 0.f, S2 = 0.f, Mx = -3.4028235e38f, Mn = 3.4028235e38f;
    const float* Zb = g_Z + (size_t)b * NPTS * 32;
#pragma unroll 5
    for (int k = 0; k < KNN; ++k) {
        int j = s_idx[warp*KNN + k];
        float z = Zb[(size_t)j*32 + lane];
        S1 += z;
        S2 = fmaf(z, z, S2);
        Mx = fmaxf(Mx, z);
        Mn = fminf(Mn, z);
    }
    const size_t pi = (size_t)(b*NPTS + n)*32 + lane;
    const float t = g_T[pi];
    g_Pmx[pi] = Mx + t;
    g_Pmn[pi] = Mn + t;
    double ssum = (double)S1 + (double)KNN * (double)t;
    double qsum = (double)S2 + 2.0*(double)t*(double)S1 + (double)KNN * (double)t * (double)t;

    s_red[warp*32 + lane]       = ssum;
    s_red[256 + warp*32 + lane] = qsum;
    __syncthreads();
    if (warp == 0) {
        double a = 0.0, c = 0.0;
#pragma unroll
        for (int w = 0; w < 8; ++w) { a += s_red[w*32 + lane]; c += s_red[256 + w*32 + lane]; }
        atomicAdd(&g_stats[lane],      a);
        atomicAdd(&g_stats[32 + lane], c);
    }
}

// ------------- standalone pass-d for layer 4 -------------
__global__ void __launch_bounds__(256) pass_d(int layer, const float* __restrict__ gamma,
                                              const float* __restrict__ beta)
{
    const int b = blockIdx.y;
    const int n = blockIdx.x * 8 + (threadIdx.x >> 5);
    const int o = threadIdx.x & 31;

    const double cnt = (double)B * (double)NPTS * (double)KNN;
    double meand = g_stats[o] / cnt;
    double vard  = g_stats[32 + o] / cnt - meand * meand;
    float inv  = rsqrtf((float)vard + 1e-5f);
    float sc = gamma[o] * inv;
    float sh = beta[o] - (float)meand * sc;

    size_t pi = (size_t)(b*NPTS + n)*32 + o;
    float pre = (sc >= 0.f) ? g_Pmx[pi] : g_Pmn[pi];
    float y = fmaf(pre, sc, sh);
    y = (y >= 0.f) ? y : 0.2f * y;
    size_t ci = (size_t)(b*NPTS + n) * 128;
    if (layer > 1) y += g_xcat[ci + 32*(layer - 2) + o];
    g_xcat[ci + 32*(layer - 1) + o] = y;
}

// ------------- out[b,o,n] = sum_c W5[o,c] * cat[b,c,n] -------------
__global__ void __launch_bounds__(128) final_gemm(const float* __restrict__ W5,
                                                  float* __restrict__ out)
{
    __shared__ float s[32*128];
    const int b = blockIdx.y, n0 = blockIdx.x * 32, t = threadIdx.x;
    const float* src = g_xcat + (size_t)(b*NPTS + n0) * 128;
    for (int i = t; i < 32*128/4; i += 128)
        ((float4*)s)[i] = ((const float4*)src)[i];
    __syncthreads();

    float acc[32];
#pragma unroll
    for (int n = 0; n < 32; ++n) acc[n] = 0.f;
    const float4* Wrow = (const float4*)(W5 + (size_t)t * 128);
#pragma unroll 8
    for (int c4 = 0; c4 < 32; ++c4) {
        float4 w = __ldg(Wrow + c4);
#pragma unroll
        for (int n = 0; n < 32; ++n) {
            float4 xv = ((const float4*)s)[n*32 + c4];
            acc[n] = fmaf(w.x, xv.x, acc[n]);
            acc[n] = fmaf(w.y, xv.y, acc[n]);
            acc[n] = fmaf(w.z, xv.z, acc[n]);
            acc[n] = fmaf(w.w, xv.w, acc[n]);
        }
    }
    __syncthreads();
#pragma unroll
    for (int n = 0; n < 32; ++n) s[t*32 + n] = acc[n];
    __syncthreads();
    for (int i = t; i < 128*32; i += 128) {
        int o = i >> 5, n = i & 31;
        out[(size_t)(b*128 + o)*NPTS + n0 + n] = s[o*32 + n];
    }
}

// ------------------------------- host -------------------------------
extern "C" void kernel_launch(void* const* d_in, const int* in_sizes, int n_in,
                              void* d_out, int out_size)
{
    const float* x  = (const float*)d_in[0];
    const float* W1 = (const float*)d_in[1];
    const float* W2 = (const float*)d_in[2];
    const float* W3 = (const float*)d_in[3];
    const float* W4 = (const float*)d_in[4];
    const float* W5 = (const float*)d_in[5];
    const float* g1 = (const float*)d_in[6],  *b1 = (const float*)d_in[7];
    const float* g2 = (const float*)d_in[8],  *b2 = (const float*)d_in[9];
    const float* g3 = (const float*)d_in[10], *b3 = (const float*)d_in[11];
    const float* g4 = (const float*)d_in[12], *b4 = (const float*)d_in[13];
    float* out = (float*)d_out;

    dim3 g8(NPTS/8, B);
    dim3 gT(NPTS/256, B);
    dim3 gG(NPTS/128, NPTS/128, B);

    transpose_pad<<<gT, 256>>>(x);

    // layer 1 (input: padded x, C=9 (pad 12), SP=12)
    zt_first<<<g8, 256>>>(W1);
    dist_gemm<12><<<gG, 256>>>(0, 0, 12);
    knn_sel<12><<<g8, 256>>>(0, 0, 12);

    // layer 2 (pass_d(1) fused; input: x1 = slice 0)
    zt_fused<<<g8, 256>>>(1, g1, b1, W2);
    dist_gemm<32><<<gG, 256>>>(1, 0, 128);
    knn_sel<32><<<g8, 256>>>(1, 0, 128);

    // layer 3
    zt_fused<<<g8, 256>>>(2, g2, b2, W3);
    dist_gemm<32><<<gG, 256>>>(1, 32, 128);
    knn_sel<32><<<g8, 256>>>(1, 32, 128);

    // layer 4
    zt_fused<<<g8, 256>>>(3, g3, b3, W4);
    dist_gemm<32><<<gG, 256>>>(1, 64, 128);
    knn_sel<32><<<g8, 256>>>(1, 64, 128);

    pass_d<<<g8, 256>>>(4, g4, b4);
    final_gemm<<<dim3(NPTS/32, B), 128>>>(W5, out);
}

// round 15
// speedup vs baseline: 2.7691x; 1.0690x over previous
#include <cuda_runtime.h>
#include <cstdint>

#define B 8
#define NPTS 2048
#define KNN 40
#define UMAXK 0xffffffffu
#define FULLM 0xffffffffu
#define CCAP 192

// ------------- static device scratch (no allocations) -------------
__device__ __align__(16) float g_xp0 [B*NPTS*12];   // layer-1 input, point-major, padded 9->12
__device__ __align__(16) float g_xcat[B*NPTS*128];  // x1..x4 point-major slices
__device__ __align__(16) float g_Z   [B*NPTS*32];
__device__ __align__(16) float g_T   [B*NPTS*32];
__device__ __align__(16) float g_Pmx [B*NPTS*32];
__device__ __align__(16) float g_Pmn [B*NPTS*32];
__device__ __align__(16) unsigned short g_keys16[(size_t)B*NPTS*NPTS];  // 67 MB truncated keys
__device__ float  g_xx[B*NPTS];
__device__ double g_stats[64];

__device__ __forceinline__ unsigned fkey(float f) {
    unsigned u = __float_as_uint(f);
    return (u & 0x80000000u) ? ~u : (u | 0x80000000u);   // monotone float -> uint
}

// packed f32x2 helpers (Blackwell): FFMA2 via PTX fma.rn.f32x2
__device__ __forceinline__ unsigned long long pk2(float lo, float hi) {
    unsigned long long r;
    asm("mov.b64 %0, {%1, %2};" : "=l"(r) : "f"(lo), "f"(hi));
    return r;
}
__device__ __forceinline__ void upk2(unsigned long long v, float& lo, float& hi) {
    asm("mov.b64 {%0, %1}, %2;" : "=f"(lo), "=f"(hi) : "l"(v));
}
__device__ __forceinline__ void ffma2(unsigned long long& d, unsigned long long a, unsigned long long b) {
    asm("fma.rn.f32x2 %0, %1, %2, %0;" : "+l"(d) : "l"(a), "l"(b));
}

// ------------- transpose + zero-pad x: (B,9,N) -> [b][n][12] -------------
__global__ void transpose_pad(const float* __restrict__ x)
{
    const int b = blockIdx.y;
    const int n = blockIdx.x * 256 + threadIdx.x;
    float* dst = g_xp0 + (size_t)(b*NPTS + n) * 12;
#pragma unroll
    for (int c = 0; c < 9; ++c) dst[c] = x[(size_t)(b*9 + c)*NPTS + n];
    dst[9] = 0.f; dst[10] = 0.f; dst[11] = 0.f;
}

// ------------- layer-1 ZT: Z = Wa*x, T = (Wb-Wa)*x, xx = ||x||^2 -------------
__global__ void __launch_bounds__(256) zt_first(const float* __restrict__ W)
{
    __shared__ float sx[8*32];
    __shared__ float sW[32*65];
    const int b  = blockIdx.y;
    const int n0 = blockIdx.x * 8;
    const int t  = threadIdx.x;
    const int C = 9, SP = 12;

    for (int i = t; i < 32*64; i += 256) {
        int o = i >> 6, c = i & 63;
        sW[o*65 + c] = (c < 2*C) ? W[o*2*C + c] : 0.f;
    }
    {
        int p = t >> 5, c = t & 31;
        sx[p*32 + c] = (c < C) ? g_xp0[(size_t)(b*NPTS + n0 + p)*SP + c] : 0.f;
    }
    __syncthreads();

    const int p = t >> 5, o = t & 31;
    float z = 0.f, tt = 0.f;
    for (int c = 0; c < C; ++c) {
        float xv = sx[p*32 + c];
        z  = fmaf(sW[o*65 + c], xv, z);
        tt = fmaf(sW[o*65 + C + c] - sW[o*65 + c], xv, tt);
    }
    size_t idx = (size_t)(b*NPTS + n0 + p)*32 + o;
    g_Z[idx] = z;
    g_T[idx] = tt;

    if (t < 8) {
        float xx = 0.f;
        for (int c = 0; c < C; ++c) { float v = sx[t*32 + c]; xx = fmaf(v, v, xx); }
        g_xx[b*NPTS + n0 + t] = xx;
    }
}

// ------------- fused: BN finalize + affine + leakyrelu + residual (prev layer) THEN ZT (next) -------------
__global__ void __launch_bounds__(256) zt_fused(int prevLayer, const float* __restrict__ gamma,
                                                const float* __restrict__ beta,
                                                const float* __restrict__ W)
{
    __shared__ float sx[8*32];
    __shared__ float sW[32*65];
    const int b  = blockIdx.y;
    const int n0 = blockIdx.x * 8;
    const int t  = threadIdx.x;
    const int p = t >> 5, o = t & 31;

    for (int i = t; i < 32*64; i += 256) {
        int oo = i >> 6, c = i & 63;
        sW[oo*65 + c] = W[oo*64 + c];
    }

    // ---- pass-d for prevLayer ----
    const double cnt = (double)B * (double)NPTS * (double)KNN;
    double meand = g_stats[o] / cnt;
    double vard  = g_stats[32 + o] / cnt - meand * meand;
    float inv  = rsqrtf((float)vard + 1e-5f);
    float sc = gamma[o] * inv;
    float sh = beta[o] - (float)meand * sc;

    size_t pi = (size_t)(b*NPTS + n0 + p)*32 + o;
    float pre = (sc >= 0.f) ? g_Pmx[pi] : g_Pmn[pi];   // max commutes through monotone map
    float y = fmaf(pre, sc, sh);
    y = (y >= 0.f) ? y : 0.2f * y;
    size_t ci = (size_t)(b*NPTS + n0 + p) * 128;
    if (prevLayer > 1) y += g_xcat[ci + 32*(prevLayer - 2) + o];
    g_xcat[ci + 32*(prevLayer - 1) + o] = y;
    sx[p*32 + o] = y;
    __syncthreads();

    // ---- ZT for layer prevLayer+1 (C=32) ----
    float z = 0.f, tt = 0.f;
    for (int c = 0; c < 32; ++c) {
        float xv = sx[p*32 + c];
        z  = fmaf(sW[o*65 + c], xv, z);
        tt = fmaf(sW[o*65 + 32 + c] - sW[o*65 + c], xv, tt);
    }
    g_Z[pi] = z;
    g_T[pi] = tt;

    if (t < 8) {
        float xx = 0.f;
        for (int c = 0; c < 32; ++c) { float v = sx[t*32 + c]; xx = fmaf(v, v, xx); }
        g_xx[b*NPTS + n0 + t] = xx;
    }
}

// ------------- distance GEMM -> truncated u16 keys; also zeroes BN stats -------------
template<int C>
__global__ void __launch_bounds__(256) dist_gemm(int which, int xoff, int SP)
{
    __shared__ float Qs[C][128];
    __shared__ float Ms[C][128];
    const int b  = blockIdx.z;
    const int n0 = blockIdx.y * 128;
    const int m0 = blockIdx.x * 128;
    const float* __restrict__ base = which ? (g_xcat + xoff) : g_xp0;

    if (blockIdx.x == 0 && blockIdx.y == 0 && b == 0 && threadIdx.x < 64)
        g_stats[threadIdx.x] = 0.0;     // zero BN accumulators for this layer

    for (int i = threadIdx.x; i < 128*(C/4); i += 256) {
        int c4 = i >> 7, p = i & 127;
        float4 vq = *(const float4*)(base + (size_t)(b*NPTS + n0 + p)*SP + c4*4);
        float4 vm = *(const float4*)(base + (size_t)(b*NPTS + m0 + p)*SP + c4*4);
        Qs[c4*4+0][p] = vq.x; Qs[c4*4+1][p] = vq.y; Qs[c4*4+2][p] = vq.z; Qs[c4*4+3][p] = vq.w;
        Ms[c4*4+0][p] = vm.x; Ms[c4*4+1][p] = vm.y; Ms[c4*4+2][p] = vm.z; Ms[c4*4+3][p] = vm.w;
    }
    __syncthreads();

    const int tx = threadIdx.x & 15;          // m direction
    const int ty = threadIdx.x >> 4;          // n direction

    unsigned long long acc2[8][4];
#pragma unroll
    for (int i = 0; i < 8; ++i)
#pragma unroll
        for (int j2 = 0; j2 < 4; ++j2) acc2[i][j2] = 0ull;

#pragma unroll
    for (int c = 0; c < C; ++c) {
        float qf[8], mf[8];
        *(float4*)(qf)     = *(const float4*)&Qs[c][ty*8];
        *(float4*)(qf + 4) = *(const float4*)&Qs[c][ty*8 + 4];
        *(float4*)(mf)     = *(const float4*)&Ms[c][tx*8];
        *(float4*)(mf + 4) = *(const float4*)&Ms[c][tx*8 + 4];
        unsigned long long mm[4];
#pragma unroll
        for (int j2 = 0; j2 < 4; ++j2) mm[j2] = pk2(mf[2*j2], mf[2*j2+1]);
#pragma unroll
        for (int i = 0; i < 8; ++i) {
            unsigned long long qq = pk2(qf[i], qf[i]);
#pragma unroll
            for (int j2 = 0; j2 < 4; ++j2) ffma2(acc2[i][j2], qq, mm[j2]);
        }
    }

    float xn[8], xm[8];
#pragma unroll
    for (int i = 0; i < 8; ++i) xn[i] = g_xx[b*NPTS + n0 + ty*8 + i];
#pragma unroll
    for (int j = 0; j < 8; ++j) xm[j] = g_xx[b*NPTS + m0 + tx*8 + j];

#pragma unroll
    for (int i = 0; i < 8; ++i) {
        float accr[8];
#pragma unroll
        for (int j2 = 0; j2 < 4; ++j2) upk2(acc2[i][j2], accr[2*j2], accr[2*j2+1]);
        unsigned kv[8];
#pragma unroll
        for (int j = 0; j < 8; ++j) {
            float d = __fadd_rn(__fsub_rn(xn[i], __fmul_rn(2.f, accr[j])), xm[j]);
            kv[j] = fkey(d);
        }
        uint4 w;
        w.x = __byte_perm(kv[0], kv[1], 0x7632);
        w.y = __byte_perm(kv[2], kv[3], 0x7632);
        w.z = __byte_perm(kv[4], kv[5], 0x7632);
        w.w = __byte_perm(kv[6], kv[7], 0x7632);
        unsigned short* dst = g_keys16 + ((size_t)(b*NPTS + n0 + ty*8 + i))*NPTS + m0 + tx*8;
        *(uint4*)dst = w;
    }
}

// ------------- selection: SIMD u16 scan -> pool-rank-40 threshold -> collect -> recompute -> set-trim -------------
template<int CP>
__global__ void __launch_bounds__(256, 4) knn_sel(int which, int xoff, int SP)
{
    __shared__ unsigned s_list[8][CCAP];
    __shared__ float    s_q[8][CP];
    __shared__ int      s_cnt[8];
    __shared__ int      s_ncnt[8];
    __shared__ int      s_idx[8*KNN];
    __shared__ double   s_red[512];

    const int b    = blockIdx.y;
    const int warp = threadIdx.x >> 5;
    const int lane = threadIdx.x & 31;
    const int n    = blockIdx.x * 8 + warp;
    const float* __restrict__ base = which ? (g_xcat + xoff) : g_xp0;

    const uint4* __restrict__ krow4 =
        (const uint4*)(g_keys16 + ((size_t)(b*NPTS + n))*NPTS);

    if (lane == 0) { s_cnt[warp] = 0; s_ncnt[warp] = 0; }
    if (lane < CP) s_q[warp][lane] = base[(size_t)(b*NPTS + n)*SP + lane];
    __syncwarp();

    // ---- pass 1: SIMD per-halfword top-2 (3 ops per packed word) ----
    unsigned A0 = UMAXK, A1 = UMAXK;
#pragma unroll 4
    for (int s = 0; s < 8; ++s) {
        uint4 kv = krow4[s*32 + lane];
        unsigned h;
        h = __vmaxu2(kv.x, A0); A0 = __vminu2(kv.x, A0); A1 = __vminu2(h, A1);
        h = __vmaxu2(kv.y, A0); A0 = __vminu2(kv.y, A0); A1 = __vminu2(h, A1);
        h = __vmaxu2(kv.z, A0); A0 = __vminu2(kv.z, A0); A1 = __vminu2(h, A1);
        h = __vmaxu2(kv.w, A0); A0 = __vminu2(kv.w, A0); A1 = __vminu2(h, A1);
    }
    // recover per-lane top-2: k0 = min(A0.lo,A0.hi); k1 = min(max(A0.lo,A0.hi), min(A1.lo,A1.hi))
    unsigned v0, v1;
    {
        unsigned a0l = A0 & 0xffffu, a0h = A0 >> 16;
        unsigned a1m = umin(A1 & 0xffffu, A1 >> 16);
        v0 = umin(a0l, a0h);
        v1 = umin(umax(a0l, a0h), a1m);
    }

    // ---- threshold: pool-rank-40 of the 64-key pool via 24 max-pops (== R14's T exactly) ----
    // lane state: elements {v0, v1}, v1 >= v0; pop max -> v1 = v0, v0 = 0 (0 = removed sentinel,
    // unreachable as a real key16 since d is never hugely negative).
    for (int r = 0; r < 24; ++r) {
        unsigned mx = __reduce_max_sync(FULLM, v1);
        unsigned bal = __ballot_sync(FULLM, v1 == mx);
        if (lane == (unsigned)(31 - __clz(bal))) { v1 = v0; v0 = 0; }
    }
    const unsigned T = __reduce_max_sync(FULLM, v1);

    // ---- collect: all m with key16 <= T (L1-resident reread; count >= 40 guaranteed) ----
#pragma unroll 4
    for (int s = 0; s < 8; ++s) {
        uint4 kv = krow4[s*32 + lane];
        unsigned w[4] = {kv.x, kv.y, kv.z, kv.w};
        const int mb = (s*32 + lane)*8;
#pragma unroll
        for (int wi = 0; wi < 4; ++wi) {
            unsigned lo = w[wi] & 0xffffu, hi = w[wi] >> 16;
            if (lo <= T) { int pos = atomicAdd(&s_cnt[warp], 1); if (pos < CCAP) s_list[warp][pos] = mb + wi*2; }
            if (hi <= T) { int pos = atomicAdd(&s_cnt[warp], 1); if (pos < CCAP) s_list[warp][pos] = mb + wi*2 + 1; }
        }
    }
    __syncwarp();
    const int Q = min(s_cnt[warp], CCAP);

    // ---- recompute exact key32 per candidate (bit-identical chain to dist_gemm; q from smem) ----
    const float xxq = g_xx[b*NPTS + n];
    unsigned long long cand[6];
#pragma unroll
    for (int r = 0; r < 6; ++r) {
        cand[r] = 0ull;                       // 0 = empty sentinel (sorts to front)
        int idx = r*32 + lane;
        if (idx < Q) {
            int m = s_list[warp][idx];
            const float4* cp4 = (const float4*)(base + (size_t)(b*NPTS + m) * SP);
            const float4* qp4 = (const float4*)(s_q[warp]);
            float dot = 0.f;
#pragma unroll
            for (int c4 = 0; c4 < CP/4; ++c4) {
                float4 v = cp4[c4];
                float4 qv = qp4[c4];
                dot = fmaf(v.x, qv.x, dot);
                dot = fmaf(v.y, qv.y, dot);
                dot = fmaf(v.z, qv.z, dot);
                dot = fmaf(v.w, qv.w, dot);
            }
            float d = __fadd_rn(__fsub_rn(xxq, __fmul_rn(2.f, dot)), g_xx[b*NPTS + m]);
            cand[r] = ((unsigned long long)fkey(d) << 32) | (unsigned)m;
        }
    }
    // ascending sort-6 (Bose-Nelson); empties (0) first, lane max at cand[5]
    {
        unsigned long long t;
#define CE(a,bq) if (cand[a] > cand[bq]) { t = cand[a]; cand[a] = cand[bq]; cand[bq] = t; }
        CE(1,2) CE(4,5) CE(0,2) CE(3,5) CE(0,1) CE(3,4)
        CE(2,5) CE(0,3) CE(1,4) CE(2,4) CE(1,3) CE(2,3)
#undef CE
    }

    // ---- set-trim: pop the (Q-40) lex-LARGEST (key, m); survivors are exactly the top-40 set ----
    const int nPop = Q - KNN;
    for (int r = 0; r < nPop; ++r) {
        unsigned hi = (unsigned)(cand[5] >> 32);
        unsigned kmax = __reduce_max_sync(FULLM, hi);
        bool tied = (hi == kmax);
        unsigned msel = __reduce_max_sync(FULLM, tied ? (unsigned)cand[5] : 0u);
        if (tied && (unsigned)cand[5] == msel) {
            cand[5] = cand[4]; cand[4] = cand[3]; cand[3] = cand[2];
            cand[2] = cand[1]; cand[1] = cand[0]; cand[0] = 0ull;
        }
    }
    // write surviving indices (order-free set)
#pragma unroll
    for (int r = 0; r < 6; ++r) {
        if (cand[r] != 0ull) {
            int p = atomicAdd(&s_ncnt[warp], 1);
            s_idx[warp*KNN + p] = (int)(unsigned)cand[r];
        }
    }
    __syncwarp();

    // ---- gather neighbor Z rows (128B coalesced), per-channel partials ----
    float S1 = 0.f, S2 = 0.f, Mx = -3.4028235e38f, Mn = 3.4028235e38f;
    const float* Zb = g_Z + (size_t)b * NPTS * 32;
#pragma unroll 5
    for (int k = 0; k < KNN; ++k) {
        int j = s_idx[warp*KNN + k];
        float z = Zb[(size_t)j*32 + lane];
        S1 += z;
        S2 = fmaf(z, z, S2);
        Mx = fmaxf(Mx, z);
        Mn = fminf(Mn, z);
    }
    const size_t pi = (size_t)(b*NPTS + n)*32 + lane;
    const float t = g_T[pi];
    g_Pmx[pi] = Mx + t;
    g_Pmn[pi] = Mn + t;
    double ssum = (double)S1 + (double)KNN * (double)t;
    double qsum = (double)S2 + 2.0*(double)t*(double)S1 + (double)KNN * (double)t * (double)t;

    s_red[warp*32 + lane]       = ssum;
    s_red[256 + warp*32 + lane] = qsum;
    __syncthreads();
    if (warp == 0) {
        double a = 0.0, c = 0.0;
#pragma unroll
        for (int w = 0; w < 8; ++w) { a += s_red[w*32 + lane]; c += s_red[256 + w*32 + lane]; }
        atomicAdd(&g_stats[lane],      a);
        atomicAdd(&g_stats[32 + lane], c);
    }
}

// ------------- standalone pass-d for layer 4 -------------
__global__ void __launch_bounds__(256) pass_d(int layer, const float* __restrict__ gamma,
                                              const float* __restrict__ beta)
{
    const int b = blockIdx.y;
    const int n = blockIdx.x * 8 + (threadIdx.x >> 5);
    const int o = threadIdx.x & 31;

    const double cnt = (double)B * (double)NPTS * (double)KNN;
    double meand = g_stats[o] / cnt;
    double vard  = g_stats[32 + o] / cnt - meand * meand;
    float inv  = rsqrtf((float)vard + 1e-5f);
    float sc = gamma[o] * inv;
    float sh = beta[o] - (float)meand * sc;

    size_t pi = (size_t)(b*NPTS + n)*32 + o;
    float pre = (sc >= 0.f) ? g_Pmx[pi] : g_Pmn[pi];
    float y = fmaf(pre, sc, sh);
    y = (y >= 0.f) ? y : 0.2f * y;
    size_t ci = (size_t)(b*NPTS + n) * 128;
    if (layer > 1) y += g_xcat[ci + 32*(layer - 2) + o];
    g_xcat[ci + 32*(layer - 1) + o] = y;
}

// ------------- out[b,o,n] = sum_c W5[o,c] * cat[b,c,n] -------------
__global__ void __launch_bounds__(128) final_gemm(const float* __restrict__ W5,
                                                  float* __restrict__ out)
{
    __shared__ float s[32*128];
    const int b = blockIdx.y, n0 = blockIdx.x * 32, t = threadIdx.x;
    const float* src = g_xcat + (size_t)(b*NPTS + n0) * 128;
    for (int i = t; i < 32*128/4; i += 128)
        ((float4*)s)[i] = ((const float4*)src)[i];
    __syncthreads();

    float acc[32];
#pragma unroll
    for (int n = 0; n < 32; ++n) acc[n] = 0.f;
    const float4* Wrow = (const float4*)(W5 + (size_t)t * 128);
#pragma unroll 8
    for (int c4 = 0; c4 < 32; ++c4) {
        float4 w = __ldg(Wrow + c4);
#pragma unroll
        for (int n = 0; n < 32; ++n) {
            float4 xv = ((const float4*)s)[n*32 + c4];
            acc[n] = fmaf(w.x, xv.x, acc[n]);
            acc[n] = fmaf(w.y, xv.y, acc[n]);
            acc[n] = fmaf(w.z, xv.z, acc[n]);
            acc[n] = fmaf(w.w, xv.w, acc[n]);
        }
    }
    __syncthreads();
#pragma unroll
    for (int n = 0; n < 32; ++n) s[t*32 + n] = acc[n];
    __syncthreads();
    for (int i = t; i < 128*32; i += 128) {
        int o = i >> 5, n = i & 31;
        out[(size_t)(b*128 + o)*NPTS + n0 + n] = s[o*32 + n];
    }
}

// ------------------------------- host -------------------------------
extern "C" void kernel_launch(void* const* d_in, const int* in_sizes, int n_in,
                              void* d_out, int out_size)
{
    const float* x  = (const float*)d_in[0];
    const float* W1 = (const float*)d_in[1];
    const float* W2 = (const float*)d_in[2];
    const float* W3 = (const float*)d_in[3];
    const float* W4 = (const float*)d_in[4];
    const float* W5 = (const float*)d_in[5];
    const float* g1 = (const float*)d_in[6],  *b1 = (const float*)d_in[7];
    const float* g2 = (const float*)d_in[8],  *b2 = (const float*)d_in[9];
    const float* g3 = (const float*)d_in[10], *b3 = (const float*)d_in[11];
    const float* g4 = (const float*)d_in[12], *b4 = (const float*)d_in[13];
    float* out = (float*)d_out;

    dim3 g8(NPTS/8, B);
    dim3 gT(NPTS/256, B);
    dim3 gG(NPTS/128, NPTS/128, B);

    transpose_pad<<<gT, 256>>>(x);

    // layer 1 (input: padded x, C=9 (pad 12), SP=12)
    zt_first<<<g8, 256>>>(W1);
    dist_gemm<12><<<gG, 256>>>(0, 0, 12);
    knn_sel<12><<<g8, 256>>>(0, 0, 12);

    // layer 2 (pass_d(1) fused; input: x1 = slice 0)
    zt_fused<<<g8, 256>>>(1, g1, b1, W2);
    dist_gemm<32><<<gG, 256>>>(1, 0, 128);
    knn_sel<32><<<g8, 256>>>(1, 0, 128);

    // layer 3
    zt_fused<<<g8, 256>>>(2, g2, b2, W3);
    dist_gemm<32><<<gG, 256>>>(1, 32, 128);
    knn_sel<32><<<g8, 256>>>(1, 32, 128);

    // layer 4
    zt_fused<<<g8, 256>>>(3, g3, b3, W4);
    dist_gemm<32><<<gG, 256>>>(1, 64, 128);
    knn_sel<32><<<g8, 256>>>(1, 64, 128);

    pass_d<<<g8, 256>>>(4, g4, b4);
    final_gemm<<<dim3(NPTS/32, B), 128>>>(W5, out);
}

// round 16
// speedup vs baseline: 2.8773x; 1.0391x over previous
#include <cuda_runtime.h>
#include <cstdint>

#define B 8
#define NPTS 2048
#define KNN 40
#define UMAXK 0xffffffffu
#define FULLM 0xffffffffu
#define CCAP 192

// ------------- static device scratch (no allocations) -------------
__device__ __align__(16) float g_xp0 [B*NPTS*12];   // layer-1 input, point-major, padded 9->12
__device__ __align__(16) float g_xcat[B*NPTS*128];  // x1..x4 point-major slices
__device__ __align__(16) float g_Z   [B*NPTS*32];
__device__ __align__(16) float g_T   [B*NPTS*32];
__device__ __align__(16) float g_Pmx [B*NPTS*32];
__device__ __align__(16) float g_Pmn [B*NPTS*32];
__device__ __align__(16) unsigned short g_keys16[(size_t)B*NPTS*NPTS];  // 67 MB truncated keys
__device__ float  g_xx[B*NPTS];
__device__ double g_stats[64];

__device__ __forceinline__ unsigned fkey(float f) {
    unsigned u = __float_as_uint(f);
    return (u & 0x80000000u) ? ~u : (u | 0x80000000u);   // monotone float -> uint
}

// packed f32x2 helpers (Blackwell): FFMA2 via PTX fma.rn.f32x2
__device__ __forceinline__ unsigned long long pk2(float lo, float hi) {
    unsigned long long r;
    asm("mov.b64 %0, {%1, %2};" : "=l"(r) : "f"(lo), "f"(hi));
    return r;
}
__device__ __forceinline__ void upk2(unsigned long long v, float& lo, float& hi) {
    asm("mov.b64 {%0, %1}, %2;" : "=f"(lo), "=f"(hi) : "l"(v));
}
__device__ __forceinline__ void ffma2(unsigned long long& d, unsigned long long a, unsigned long long b) {
    asm("fma.rn.f32x2 %0, %1, %2, %0;" : "+l"(d) : "l"(a), "l"(b));
}

// ------------- transpose + zero-pad x: (B,9,N) -> [b][n][12] -------------
__global__ void transpose_pad(const float* __restrict__ x)
{
    const int b = blockIdx.y;
    const int n = blockIdx.x * 256 + threadIdx.x;
    float* dst = g_xp0 + (size_t)(b*NPTS + n) * 12;
#pragma unroll
    for (int c = 0; c < 9; ++c) dst[c] = x[(size_t)(b*9 + c)*NPTS + n];
    dst[9] = 0.f; dst[10] = 0.f; dst[11] = 0.f;
}

// ------------- layer-1 ZT: Z = Wa*x, T = (Wb-Wa)*x, xx = ||x||^2 -------------
__global__ void __launch_bounds__(256) zt_first(const float* __restrict__ W)
{
    __shared__ float sx[8*32];
    __shared__ float sW[32*65];
    const int b  = blockIdx.y;
    const int n0 = blockIdx.x * 8;
    const int t  = threadIdx.x;
    const int C = 9, SP = 12;

    for (int i = t; i < 32*64; i += 256) {
        int o = i >> 6, c = i & 63;
        sW[o*65 + c] = (c < 2*C) ? W[o*2*C + c] : 0.f;
    }
    {
        int p = t >> 5, c = t & 31;
        sx[p*32 + c] = (c < C) ? g_xp0[(size_t)(b*NPTS + n0 + p)*SP + c] : 0.f;
    }
    __syncthreads();

    const int p = t >> 5, o = t & 31;
    float z = 0.f, tt = 0.f;
    for (int c = 0; c < C; ++c) {
        float xv = sx[p*32 + c];
        z  = fmaf(sW[o*65 + c], xv, z);
        tt = fmaf(sW[o*65 + C + c] - sW[o*65 + c], xv, tt);
    }
    size_t idx = (size_t)(b*NPTS + n0 + p)*32 + o;
    g_Z[idx] = z;
    g_T[idx] = tt;

    if (t < 8) {
        float xx = 0.f;
        for (int c = 0; c < C; ++c) { float v = sx[t*32 + c]; xx = fmaf(v, v, xx); }
        g_xx[b*NPTS + n0 + t] = xx;
    }
}

// ------------- fused: BN finalize + affine + leakyrelu + residual (prev layer) THEN ZT (next) -------------
__global__ void __launch_bounds__(256) zt_fused(int prevLayer, const float* __restrict__ gamma,
                                                const float* __restrict__ beta,
                                                const float* __restrict__ W)
{
    __shared__ float sx[8*32];
    __shared__ float sW[32*65];
    const int b  = blockIdx.y;
    const int n0 = blockIdx.x * 8;
    const int t  = threadIdx.x;
    const int p = t >> 5, o = t & 31;

    for (int i = t; i < 32*64; i += 256) {
        int oo = i >> 6, c = i & 63;
        sW[oo*65 + c] = W[oo*64 + c];
    }

    // ---- pass-d for prevLayer ----
    const double cnt = (double)B * (double)NPTS * (double)KNN;
    double meand = g_stats[o] / cnt;
    double vard  = g_stats[32 + o] / cnt - meand * meand;
    float inv  = rsqrtf((float)vard + 1e-5f);
    float sc = gamma[o] * inv;
    float sh = beta[o] - (float)meand * sc;

    size_t pi = (size_t)(b*NPTS + n0 + p)*32 + o;
    float pre = (sc >= 0.f) ? g_Pmx[pi] : g_Pmn[pi];   // max commutes through monotone map
    float y = fmaf(pre, sc, sh);
    y = (y >= 0.f) ? y : 0.2f * y;
    size_t ci = (size_t)(b*NPTS + n0 + p) * 128;
    if (prevLayer > 1) y += g_xcat[ci + 32*(prevLayer - 2) + o];
    g_xcat[ci + 32*(prevLayer - 1) + o] = y;
    sx[p*32 + o] = y;
    __syncthreads();

    // ---- ZT for layer prevLayer+1 (C=32) ----
    float z = 0.f, tt = 0.f;
    for (int c = 0; c < 32; ++c) {
        float xv = sx[p*32 + c];
        z  = fmaf(sW[o*65 + c], xv, z);
        tt = fmaf(sW[o*65 + 32 + c] - sW[o*65 + c], xv, tt);
    }
    g_Z[pi] = z;
    g_T[pi] = tt;

    if (t < 8) {
        float xx = 0.f;
        for (int c = 0; c < 32; ++c) { float v = sx[t*32 + c]; xx = fmaf(v, v, xx); }
        g_xx[b*NPTS + n0 + t] = xx;
    }
}

// ------------- distance GEMM -> truncated u16 keys; also zeroes BN stats -------------
template<int C>
__global__ void __launch_bounds__(256) dist_gemm(int which, int xoff, int SP)
{
    __shared__ float Qs[C][128];
    __shared__ float Ms[C][128];
    const int b  = blockIdx.z;
    const int n0 = blockIdx.y * 128;
    const int m0 = blockIdx.x * 128;
    const float* __restrict__ base = which ? (g_xcat + xoff) : g_xp0;

    if (blockIdx.x == 0 && blockIdx.y == 0 && b == 0 && threadIdx.x < 64)
        g_stats[threadIdx.x] = 0.0;     // zero BN accumulators for this layer

    for (int i = threadIdx.x; i < 128*(C/4); i += 256) {
        int c4 = i >> 7, p = i & 127;
        float4 vq = *(const float4*)(base + (size_t)(b*NPTS + n0 + p)*SP + c4*4);
        float4 vm = *(const float4*)(base + (size_t)(b*NPTS + m0 + p)*SP + c4*4);
        Qs[c4*4+0][p] = vq.x; Qs[c4*4+1][p] = vq.y; Qs[c4*4+2][p] = vq.z; Qs[c4*4+3][p] = vq.w;
        Ms[c4*4+0][p] = vm.x; Ms[c4*4+1][p] = vm.y; Ms[c4*4+2][p] = vm.z; Ms[c4*4+3][p] = vm.w;
    }
    __syncthreads();

    const int tx = threadIdx.x & 15;          // m direction
    const int ty = threadIdx.x >> 4;          // n direction

    unsigned long long acc2[8][4];
#pragma unroll
    for (int i = 0; i < 8; ++i)
#pragma unroll
        for (int j2 = 0; j2 < 4; ++j2) acc2[i][j2] = 0ull;

#pragma unroll
    for (int c = 0; c < C; ++c) {
        float qf[8], mf[8];
        *(float4*)(qf)     = *(const float4*)&Qs[c][ty*8];
        *(float4*)(qf + 4) = *(const float4*)&Qs[c][ty*8 + 4];
        *(float4*)(mf)     = *(const float4*)&Ms[c][tx*8];
        *(float4*)(mf + 4) = *(const float4*)&Ms[c][tx*8 + 4];
        unsigned long long mm[4];
#pragma unroll
        for (int j2 = 0; j2 < 4; ++j2) mm[j2] = pk2(mf[2*j2], mf[2*j2+1]);
#pragma unroll
        for (int i = 0; i < 8; ++i) {
            unsigned long long qq = pk2(qf[i], qf[i]);
#pragma unroll
            for (int j2 = 0; j2 < 4; ++j2) ffma2(acc2[i][j2], qq, mm[j2]);
        }
    }

    float xn[8], xm[8];
#pragma unroll
    for (int i = 0; i < 8; ++i) xn[i] = g_xx[b*NPTS + n0 + ty*8 + i];
#pragma unroll
    for (int j = 0; j < 8; ++j) xm[j] = g_xx[b*NPTS + m0 + tx*8 + j];

#pragma unroll
    for (int i = 0; i < 8; ++i) {
        float accr[8];
#pragma unroll
        for (int j2 = 0; j2 < 4; ++j2) upk2(acc2[i][j2], accr[2*j2], accr[2*j2+1]);
        unsigned kv[8];
#pragma unroll
        for (int j = 0; j < 8; ++j) {
            float d = __fadd_rn(__fsub_rn(xn[i], __fmul_rn(2.f, accr[j])), xm[j]);
            kv[j] = fkey(d);
        }
        uint4 w;
        w.x = __byte_perm(kv[0], kv[1], 0x7632);
        w.y = __byte_perm(kv[2], kv[3], 0x7632);
        w.z = __byte_perm(kv[4], kv[5], 0x7632);
        w.w = __byte_perm(kv[6], kv[7], 0x7632);
        unsigned short* dst = g_keys16 + ((size_t)(b*NPTS + n0 + ty*8 + i))*NPTS + m0 + tx*8;
        *(uint4*)dst = w;
    }
}

// ------------- selection: SIMD u16 scan -> binary-search pool-rank-40 -> collect -> recompute -> set-trim -------------
template<int CP>
__global__ void __launch_bounds__(256, 5) knn_sel(int which, int xoff, int SP)
{
    __shared__ unsigned short s_list[8][CCAP];
    __shared__ float    s_q[8][CP];
    __shared__ int      s_cnt[8];
    __shared__ int      s_ncnt[8];
    __shared__ int      s_idx[8*KNN];
    __shared__ double   s_red[512];

    const int b    = blockIdx.y;
    const int warp = threadIdx.x >> 5;
    const int lane = threadIdx.x & 31;
    const int n    = blockIdx.x * 8 + warp;
    const float* __restrict__ base = which ? (g_xcat + xoff) : g_xp0;

    const uint4* __restrict__ krow4 =
        (const uint4*)(g_keys16 + ((size_t)(b*NPTS + n))*NPTS);

    if (lane == 0) { s_cnt[warp] = 0; s_ncnt[warp] = 0; }
    if (lane < CP) s_q[warp][lane] = base[(size_t)(b*NPTS + n)*SP + lane];
    __syncwarp();

    // ---- pass 1: SIMD per-halfword top-2 (3 ops per packed word) ----
    unsigned A0 = UMAXK, A1 = UMAXK;
#pragma unroll 4
    for (int s = 0; s < 8; ++s) {
        uint4 kv = krow4[s*32 + lane];
        unsigned h;
        h = __vmaxu2(kv.x, A0); A0 = __vminu2(kv.x, A0); A1 = __vminu2(h, A1);
        h = __vmaxu2(kv.y, A0); A0 = __vminu2(kv.y, A0); A1 = __vminu2(h, A1);
        h = __vmaxu2(kv.z, A0); A0 = __vminu2(kv.z, A0); A1 = __vminu2(h, A1);
        h = __vmaxu2(kv.w, A0); A0 = __vminu2(kv.w, A0); A1 = __vminu2(h, A1);
    }
    // recover per-lane top-2 of the 64-key pool partition owned by this lane
    unsigned v0, v1;
    {
        unsigned a0l = A0 & 0xffffu, a0h = A0 >> 16;
        unsigned a1m = umin(A1 & 0xffffu, A1 >> 16);
        v0 = umin(a0l, a0h);
        v1 = umin(umax(a0l, a0h), a1m);
    }

    // ---- threshold: pool-rank-40 via 16-step binary search on the u16 value domain.
    //      T = min{X : #(pool <= X) >= 40} == 40th smallest of the 64-element pool
    //      (identical to the popped value in R14/15). Uniform branches, short dep chain. ----
    unsigned lo = 0, hi = 0xffffu;
#pragma unroll
    for (int it = 0; it < 16; ++it) {
        unsigned mid = (lo + hi) >> 1;
        int cnt = __popc(__ballot_sync(FULLM, v0 <= mid)) +
                  __popc(__ballot_sync(FULLM, v1 <= mid));
        if (cnt >= KNN) hi = mid; else lo = mid + 1;
    }
    const unsigned T = hi;

    // ---- collect: all m with key16 <= T (L1-resident reread; count >= 40 guaranteed) ----
#pragma unroll 4
    for (int s = 0; s < 8; ++s) {
        uint4 kv = krow4[s*32 + lane];
        unsigned w[4] = {kv.x, kv.y, kv.z, kv.w};
        const int mb = (s*32 + lane)*8;
#pragma unroll
        for (int wi = 0; wi < 4; ++wi) {
            unsigned lov = w[wi] & 0xffffu, hiv = w[wi] >> 16;
            if (lov <= T) { int pos = atomicAdd(&s_cnt[warp], 1); if (pos < CCAP) s_list[warp][pos] = (unsigned short)(mb + wi*2); }
            if (hiv <= T) { int pos = atomicAdd(&s_cnt[warp], 1); if (pos < CCAP) s_list[warp][pos] = (unsigned short)(mb + wi*2 + 1); }
        }
    }
    __syncwarp();
    const int Q = min(s_cnt[warp], CCAP);

    // ---- recompute exact key32 per candidate (bit-identical chain to dist_gemm; q from smem) ----
    const float xxq = g_xx[b*NPTS + n];
    unsigned long long cand[6];
#pragma unroll
    for (int r = 0; r < 6; ++r) {
        cand[r] = 0ull;                       // 0 = empty sentinel (sorts to front)
        int idx = r*32 + lane;
        if (idx < Q) {
            int m = s_list[warp][idx];
            const float4* cp4 = (const float4*)(base + (size_t)(b*NPTS + m) * SP);
            const float4* qp4 = (const float4*)(s_q[warp]);
            float dot = 0.f;
#pragma unroll
            for (int c4 = 0; c4 < CP/4; ++c4) {
                float4 v = cp4[c4];
                float4 qv = qp4[c4];
                dot = fmaf(v.x, qv.x, dot);
                dot = fmaf(v.y, qv.y, dot);
                dot = fmaf(v.z, qv.z, dot);
                dot = fmaf(v.w, qv.w, dot);
            }
            float d = __fadd_rn(__fsub_rn(xxq, __fmul_rn(2.f, dot)), g_xx[b*NPTS + m]);
            cand[r] = ((unsigned long long)fkey(d) << 32) | (unsigned)m;
        }
    }
    // ascending sort-6 (Bose-Nelson); empties (0) first, lane max at cand[5]
    {
        unsigned long long t;
#define CE(a,bq) if (cand[a] > cand[bq]) { t = cand[a]; cand[a] = cand[bq]; cand[bq] = t; }
        CE(1,2) CE(4,5) CE(0,2) CE(3,5) CE(0,1) CE(3,4)
        CE(2,5) CE(0,3) CE(1,4) CE(2,4) CE(1,3) CE(2,3)
#undef CE
    }

    // ---- set-trim: pop the (Q-40) lex-LARGEST (key, m); survivors are exactly the top-40 set ----
    const int nPop = Q - KNN;
    for (int r = 0; r < nPop; ++r) {
        unsigned hi5 = (unsigned)(cand[5] >> 32);
        unsigned kmax = __reduce_max_sync(FULLM, hi5);
        bool tied = (hi5 == kmax);
        unsigned msel = __reduce_max_sync(FULLM, tied ? (unsigned)cand[5] : 0u);
        if (tied && (unsigned)cand[5] == msel) {
            cand[5] = cand[4]; cand[4] = cand[3]; cand[3] = cand[2];
            cand[2] = cand[1]; cand[1] = cand[0]; cand[0] = 0ull;
        }
    }
    // write surviving indices (order-free set)
#pragma unroll
    for (int r = 0; r < 6; ++r) {
        if (cand[r] != 0ull) {
            int p = atomicAdd(&s_ncnt[warp], 1);
            s_idx[warp*KNN + p] = (int)(unsigned)cand[r];
        }
    }
    __syncwarp();

    // ---- gather neighbor Z rows (128B coalesced), per-channel partials ----
    float S1 = 0.f, S2 = 0.f, Mx = -3.4028235e38f, Mn = 3.4028235e38f;
    const float* Zb = g_Z + (size_t)b * NPTS * 32;
#pragma unroll 5
    for (int k = 0; k < KNN; ++k) {
        int j = s_idx[warp*KNN + k];
        float z = Zb[(size_t)j*32 + lane];
        S1 += z;
        S2 = fmaf(z, z, S2);
        Mx = fmaxf(Mx, z);
        Mn = fminf(Mn, z);
    }
    const size_t pi = (size_t)(b*NPTS + n)*32 + lane;
    const float t = g_T[pi];
    g_Pmx[pi] = Mx + t;
    g_Pmn[pi] = Mn + t;
    double ssum = (double)S1 + (double)KNN * (double)t;
    double qsum = (double)S2 + 2.0*(double)t*(double)S1 + (double)KNN * (double)t * (double)t;

    s_red[warp*32 + lane]       = ssum;
    s_red[256 + warp*32 + lane] = qsum;
    __syncthreads();
    if (warp == 0) {
        double a = 0.0, c = 0.0;
#pragma unroll
        for (int w = 0; w < 8; ++w) { a += s_red[w*32 + lane]; c += s_red[256 + w*32 + lane]; }
        atomicAdd(&g_stats[lane],      a);
        atomicAdd(&g_stats[32 + lane], c);
    }
}

// ------------- standalone pass-d for layer 4 -------------
__global__ void __launch_bounds__(256) pass_d(int layer, const float* __restrict__ gamma,
                                              const float* __restrict__ beta)
{
    const int b = blockIdx.y;
    const int n = blockIdx.x * 8 + (threadIdx.x >> 5);
    const int o = threadIdx.x & 31;

    const double cnt = (double)B * (double)NPTS * (double)KNN;
    double meand = g_stats[o] / cnt;
    double vard  = g_stats[32 + o] / cnt - meand * meand;
    float inv  = rsqrtf((float)vard + 1e-5f);
    float sc = gamma[o] * inv;
    float sh = beta[o] - (float)meand * sc;

    size_t pi = (size_t)(b*NPTS + n)*32 + o;
    float pre = (sc >= 0.f) ? g_Pmx[pi] : g_Pmn[pi];
    float y = fmaf(pre, sc, sh);
    y = (y >= 0.f) ? y : 0.2f * y;
    size_t ci = (size_t)(b*NPTS + n) * 128;
    if (layer > 1) y += g_xcat[ci + 32*(layer - 2) + o];
    g_xcat[ci + 32*(layer - 1) + o] = y;
}

// ------------- out[b,o,n] = sum_c W5[o,c] * cat[b,c,n] -------------
__global__ void __launch_bounds__(128) final_gemm(const float* __restrict__ W5,
                                                  float* __restrict__ out)
{
    __shared__ float s[32*128];
    const int b = blockIdx.y, n0 = blockIdx.x * 32, t = threadIdx.x;
    const float* src = g_xcat + (size_t)(b*NPTS + n0) * 128;
    for (int i = t; i < 32*128/4; i += 128)
        ((float4*)s)[i] = ((const float4*)src)[i];
    __syncthreads();

    float acc[32];
#pragma unroll
    for (int n = 0; n < 32; ++n) acc[n] = 0.f;
    const float4* Wrow = (const float4*)(W5 + (size_t)t * 128);
#pragma unroll 8
    for (int c4 = 0; c4 < 32; ++c4) {
        float4 w = __ldg(Wrow + c4);
#pragma unroll
        for (int n = 0; n < 32; ++n) {
            float4 xv = ((const float4*)s)[n*32 + c4];
            acc[n] = fmaf(w.x, xv.x, acc[n]);
            acc[n] = fmaf(w.y, xv.y, acc[n]);
            acc[n] = fmaf(w.z, xv.z, acc[n]);
            acc[n] = fmaf(w.w, xv.w, acc[n]);
        }
    }
    __syncthreads();
#pragma unroll
    for (int n = 0; n < 32; ++n) s[t*32 + n] = acc[n];
    __syncthreads();
    for (int i = t; i < 128*32; i += 128) {
        int o = i >> 5, n = i & 31;
        out[(size_t)(b*128 + o)*NPTS + n0 + n] = s[o*32 + n];
    }
}

// ------------------------------- host -------------------------------
extern "C" void kernel_launch(void* const* d_in, const int* in_sizes, int n_in,
                              void* d_out, int out_size)
{
    const float* x  = (const float*)d_in[0];
    const float* W1 = (const float*)d_in[1];
    const float* W2 = (const float*)d_in[2];
    const float* W3 = (const float*)d_in[3];
    const float* W4 = (const float*)d_in[4];
    const float* W5 = (const float*)d_in[5];
    const float* g1 = (const float*)d_in[6],  *b1 = (const float*)d_in[7];
    const float* g2 = (const float*)d_in[8],  *b2 = (const float*)d_in[9];
    const float* g3 = (const float*)d_in[10], *b3 = (const float*)d_in[11];
    const float* g4 = (const float*)d_in[12], *b4 = (const float*)d_in[13];
    float* out = (float*)d_out;

    dim3 g8(NPTS/8, B);
    dim3 gT(NPTS/256, B);
    dim3 gG(NPTS/128, NPTS/128, B);

    transpose_pad<<<gT, 256>>>(x);

    // layer 1 (input: padded x, C=9 (pad 12), SP=12)
    zt_first<<<g8, 256>>>(W1);
    dist_gemm<12><<<gG, 256>>>(0, 0, 12);
    knn_sel<12><<<g8, 256>>>(0, 0, 12);

    // layer 2 (pass_d(1) fused; input: x1 = slice 0)
    zt_fused<<<g8, 256>>>(1, g1, b1, W2);
    dist_gemm<32><<<gG, 256>>>(1, 0, 128);
    knn_sel<32><<<g8, 256>>>(1, 0, 128);

    // layer 3
    zt_fused<<<g8, 256>>>(2, g2, b2, W3);
    dist_gemm<32><<<gG, 256>>>(1, 32, 128);
    knn_sel<32><<<g8, 256>>>(1, 32, 128);

    // layer 4
    zt_fused<<<g8, 256>>>(3, g3, b3, W4);
    dist_gemm<32><<<gG, 256>>>(1, 64, 128);
    knn_sel<32><<<g8, 256>>>(1, 64, 128);

    pass_d<<<g8, 256>>>(4, g4, b4);
    final_gemm<<<dim3(NPTS/32, B), 128>>>(W5, out);
}

// round 17
// speedup vs baseline: 2.9309x; 1.0186x over previous
#include <cuda_runtime.h>
#include <cstdint>

#define B 8
#define NPTS 2048
#define KNN 40
#define UMAXK 0xffffffffu
#define FULLM 0xffffffffu
#define CCAP 192

// ------------- static device scratch (no allocations) -------------
__device__ __align__(16) float g_xp0 [B*NPTS*12];   // layer-1 input, point-major, padded 9->12
__device__ __align__(16) float g_xcat[B*NPTS*128];  // x1..x4 point-major slices
__device__ __align__(16) float g_Z   [B*NPTS*32];
__device__ __align__(16) float g_T   [B*NPTS*32];
__device__ __align__(16) float g_Pmx [B*NPTS*32];
__device__ __align__(16) float g_Pmn [B*NPTS*32];
__device__ __align__(16) unsigned short g_keys16[(size_t)B*NPTS*NPTS];  // 67 MB truncated keys
__device__ float  g_xx[B*NPTS];
__device__ double g_stats[64];

__device__ __forceinline__ unsigned fkey(float f) {
    unsigned u = __float_as_uint(f);
    return (u & 0x80000000u) ? ~u : (u | 0x80000000u);   // monotone float -> uint
}

// packed f32x2 helpers (Blackwell): FFMA2 via PTX fma.rn.f32x2
__device__ __forceinline__ unsigned long long pk2(float lo, float hi) {
    unsigned long long r;
    asm("mov.b64 %0, {%1, %2};" : "=l"(r) : "f"(lo), "f"(hi));
    return r;
}
__device__ __forceinline__ void upk2(unsigned long long v, float& lo, float& hi) {
    asm("mov.b64 {%0, %1}, %2;" : "=f"(lo), "=f"(hi) : "l"(v));
}
__device__ __forceinline__ void ffma2(unsigned long long& d, unsigned long long a, unsigned long long b) {
    asm("fma.rn.f32x2 %0, %1, %2, %0;" : "+l"(d) : "l"(a), "l"(b));
}

// ------------- transpose + zero-pad x: (B,9,N) -> [b][n][12] -------------
__global__ void transpose_pad(const float* __restrict__ x)
{
    const int b = blockIdx.y;
    const int n = blockIdx.x * 256 + threadIdx.x;
    float* dst = g_xp0 + (size_t)(b*NPTS + n) * 12;
#pragma unroll
    for (int c = 0; c < 9; ++c) dst[c] = x[(size_t)(b*9 + c)*NPTS + n];
    dst[9] = 0.f; dst[10] = 0.f; dst[11] = 0.f;
}

// ------------- layer-1 ZT: Z = Wa*x, T = (Wb-Wa)*x, xx = ||x||^2 -------------
__global__ void __launch_bounds__(256) zt_first(const float* __restrict__ W)
{
    __shared__ float sx[8*32];
    __shared__ float sW[32*65];
    const int b  = blockIdx.y;
    const int n0 = blockIdx.x * 8;
    const int t  = threadIdx.x;
    const int C = 9, SP = 12;

    for (int i = t; i < 32*64; i += 256) {
        int o = i >> 6, c = i & 63;
        sW[o*65 + c] = (c < 2*C) ? W[o*2*C + c] : 0.f;
    }
    {
        int p = t >> 5, c = t & 31;
        sx[p*32 + c] = (c < C) ? g_xp0[(size_t)(b*NPTS + n0 + p)*SP + c] : 0.f;
    }
    __syncthreads();

    const int p = t >> 5, o = t & 31;
    float z = 0.f, tt = 0.f;
    for (int c = 0; c < C; ++c) {
        float xv = sx[p*32 + c];
        z  = fmaf(sW[o*65 + c], xv, z);
        tt = fmaf(sW[o*65 + C + c] - sW[o*65 + c], xv, tt);
    }
    size_t idx = (size_t)(b*NPTS + n0 + p)*32 + o;
    g_Z[idx] = z;
    g_T[idx] = tt;

    if (t < 8) {
        float xx = 0.f;
        for (int c = 0; c < C; ++c) { float v = sx[t*32 + c]; xx = fmaf(v, v, xx); }
        g_xx[b*NPTS + n0 + t] = xx;
    }
}

// ------------- fused: BN finalize + affine + leakyrelu + residual (prev layer) THEN ZT (next) -------------
__global__ void __launch_bounds__(256) zt_fused(int prevLayer, const float* __restrict__ gamma,
                                                const float* __restrict__ beta,
                                                const float* __restrict__ W)
{
    __shared__ float sx[8*32];
    __shared__ float sW[32*65];
    const int b  = blockIdx.y;
    const int n0 = blockIdx.x * 8;
    const int t  = threadIdx.x;
    const int p = t >> 5, o = t & 31;

    for (int i = t; i < 32*64; i += 256) {
        int oo = i >> 6, c = i & 63;
        sW[oo*65 + c] = W[oo*64 + c];
    }

    // ---- pass-d for prevLayer ----
    const double cnt = (double)B * (double)NPTS * (double)KNN;
    double meand = g_stats[o] / cnt;
    double vard  = g_stats[32 + o] / cnt - meand * meand;
    float inv  = rsqrtf((float)vard + 1e-5f);
    float sc = gamma[o] * inv;
    float sh = beta[o] - (float)meand * sc;

    size_t pi = (size_t)(b*NPTS + n0 + p)*32 + o;
    float pre = (sc >= 0.f) ? g_Pmx[pi] : g_Pmn[pi];   // max commutes through monotone map
    float y = fmaf(pre, sc, sh);
    y = (y >= 0.f) ? y : 0.2f * y;
    size_t ci = (size_t)(b*NPTS + n0 + p) * 128;
    if (prevLayer > 1) y += g_xcat[ci + 32*(prevLayer - 2) + o];
    g_xcat[ci + 32*(prevLayer - 1) + o] = y;
    sx[p*32 + o] = y;
    __syncthreads();

    // ---- ZT for layer prevLayer+1 (C=32) ----
    float z = 0.f, tt = 0.f;
    for (int c = 0; c < 32; ++c) {
        float xv = sx[p*32 + c];
        z  = fmaf(sW[o*65 + c], xv, z);
        tt = fmaf(sW[o*65 + 32 + c] - sW[o*65 + c], xv, tt);
    }
    g_Z[pi] = z;
    g_T[pi] = tt;

    if (t < 8) {
        float xx = 0.f;
        for (int c = 0; c < 32; ++c) { float v = sx[t*32 + c]; xx = fmaf(v, v, xx); }
        g_xx[b*NPTS + n0 + t] = xx;
    }
}

// ------------- distance GEMM -> truncated u16 keys; also zeroes BN stats -------------
template<int C>
__global__ void __launch_bounds__(256) dist_gemm(int which, int xoff, int SP)
{
    __shared__ float Qs[C][128];
    __shared__ float Ms[C][128];
    const int b  = blockIdx.z;
    const int n0 = blockIdx.y * 128;
    const int m0 = blockIdx.x * 128;
    const float* __restrict__ base = which ? (g_xcat + xoff) : g_xp0;

    if (blockIdx.x == 0 && blockIdx.y == 0 && b == 0 && threadIdx.x < 64)
        g_stats[threadIdx.x] = 0.0;     // zero BN accumulators for this layer

    for (int i = threadIdx.x; i < 128*(C/4); i += 256) {
        int c4 = i >> 7, p = i & 127;
        float4 vq = *(const float4*)(base + (size_t)(b*NPTS + n0 + p)*SP + c4*4);
        float4 vm = *(const float4*)(base + (size_t)(b*NPTS + m0 + p)*SP + c4*4);
        Qs[c4*4+0][p] = vq.x; Qs[c4*4+1][p] = vq.y; Qs[c4*4+2][p] = vq.z; Qs[c4*4+3][p] = vq.w;
        Ms[c4*4+0][p] = vm.x; Ms[c4*4+1][p] = vm.y; Ms[c4*4+2][p] = vm.z; Ms[c4*4+3][p] = vm.w;
    }
    __syncthreads();

    const int tx = threadIdx.x & 15;          // m direction
    const int ty = threadIdx.x >> 4;          // n direction

    unsigned long long acc2[8][4];
#pragma unroll
    for (int i = 0; i < 8; ++i)
#pragma unroll
        for (int j2 = 0; j2 < 4; ++j2) acc2[i][j2] = 0ull;

#pragma unroll
    for (int c = 0; c < C; ++c) {
        float qf[8], mf[8];
        *(float4*)(qf)     = *(const float4*)&Qs[c][ty*8];
        *(float4*)(qf + 4) = *(const float4*)&Qs[c][ty*8 + 4];
        *(float4*)(mf)     = *(const float4*)&Ms[c][tx*8];
        *(float4*)(mf + 4) = *(const float4*)&Ms[c][tx*8 + 4];
        unsigned long long mm[4];
#pragma unroll
        for (int j2 = 0; j2 < 4; ++j2) mm[j2] = pk2(mf[2*j2], mf[2*j2+1]);
#pragma unroll
        for (int i = 0; i < 8; ++i) {
            unsigned long long qq = pk2(qf[i], qf[i]);
#pragma unroll
            for (int j2 = 0; j2 < 4; ++j2) ffma2(acc2[i][j2], qq, mm[j2]);
        }
    }

    float xn[8], xm[8];
#pragma unroll
    for (int i = 0; i < 8; ++i) xn[i] = g_xx[b*NPTS + n0 + ty*8 + i];
#pragma unroll
    for (int j = 0; j < 8; ++j) xm[j] = g_xx[b*NPTS + m0 + tx*8 + j];

#pragma unroll
    for (int i = 0; i < 8; ++i) {
        float accr[8];
#pragma unroll
        for (int j2 = 0; j2 < 4; ++j2) upk2(acc2[i][j2], accr[2*j2], accr[2*j2+1]);
        unsigned kv[8];
#pragma unroll
        for (int j = 0; j < 8; ++j) {
            float d = __fadd_rn(__fsub_rn(xn[i], __fmul_rn(2.f, accr[j])), xm[j]);
            kv[j] = fkey(d);
        }
        uint4 w;
        w.x = __byte_perm(kv[0], kv[1], 0x7632);
        w.y = __byte_perm(kv[2], kv[3], 0x7632);
        w.z = __byte_perm(kv[4], kv[5], 0x7632);
        w.w = __byte_perm(kv[6], kv[7], 0x7632);
        unsigned short* dst = g_keys16 + ((size_t)(b*NPTS + n0 + ty*8 + i))*NPTS + m0 + tx*8;
        *(uint4*)dst = w;
    }
}

// ------------- selection: SIMD u16 scan -> bracketed binary-search rank-40 -> SIMD collect -> recompute -> set-trim -------------
template<int CP>
__global__ void __launch_bounds__(256, 5) knn_sel(int which, int xoff, int SP)
{
    __shared__ unsigned short s_list[8][CCAP];
    __shared__ float    s_q[8][CP];
    __shared__ int      s_cnt[8];
    __shared__ int      s_ncnt[8];
    __shared__ int      s_idx[8*KNN];
    __shared__ double   s_red[512];

    const int b    = blockIdx.y;
    const int warp = threadIdx.x >> 5;
    const int lane = threadIdx.x & 31;
    const int n    = blockIdx.x * 8 + warp;
    const float* __restrict__ base = which ? (g_xcat + xoff) : g_xp0;

    const uint4* __restrict__ krow4 =
        (const uint4*)(g_keys16 + ((size_t)(b*NPTS + n))*NPTS);

    if (lane == 0) { s_cnt[warp] = 0; s_ncnt[warp] = 0; }
    if (lane < CP) s_q[warp][lane] = base[(size_t)(b*NPTS + n)*SP + lane];
    __syncwarp();

    // ---- pass 1: SIMD per-halfword top-2 (3 ops per packed word) ----
    unsigned A0 = UMAXK, A1 = UMAXK;
#pragma unroll 4
    for (int s = 0; s < 8; ++s) {
        uint4 kv = krow4[s*32 + lane];
        unsigned h;
        h = __vmaxu2(kv.x, A0); A0 = __vminu2(kv.x, A0); A1 = __vminu2(h, A1);
        h = __vmaxu2(kv.y, A0); A0 = __vminu2(kv.y, A0); A1 = __vminu2(h, A1);
        h = __vmaxu2(kv.z, A0); A0 = __vminu2(kv.z, A0); A1 = __vminu2(h, A1);
        h = __vmaxu2(kv.w, A0); A0 = __vminu2(kv.w, A0); A1 = __vminu2(h, A1);
    }
    // recover per-lane top-2 of the 64-key pool partition owned by this lane
    unsigned v0, v1;
    {
        unsigned a0l = A0 & 0xffffu, a0h = A0 >> 16;
        unsigned a1m = umin(A1 & 0xffffu, A1 >> 16);
        v0 = umin(a0l, a0h);
        v1 = umin(umax(a0l, a0h), a1m);
    }

    // ---- threshold: pool-rank-40 via binary search bracketed to [pool-min, pool-max].
    //      Same fixed point as the full-domain search (monotone predicate, bracket contains it). ----
    unsigned lo = __reduce_min_sync(FULLM, v0);
    unsigned hi = __reduce_max_sync(FULLM, v1);
    while (lo < hi) {
        unsigned mid = (lo + hi) >> 1;
        int cnt = __popc(__ballot_sync(FULLM, v0 <= mid)) +
                  __popc(__ballot_sync(FULLM, v1 <= mid));
        if (cnt >= KNN) hi = mid; else lo = mid + 1;
    }
    const unsigned T = hi;
    const unsigned TT = T * 0x10001u;     // T in both halfwords

    // ---- collect: SIMD hit mask per word, one atomic per hit word (L1-resident reread) ----
#pragma unroll 4
    for (int s = 0; s < 8; ++s) {
        uint4 kv = krow4[s*32 + lane];
        unsigned w[4] = {kv.x, kv.y, kv.z, kv.w};
        const int mb = (s*32 + lane)*8;
#pragma unroll
        for (int wi = 0; wi < 4; ++wi) {
            unsigned hitm = __vsetleu2(w[wi], TT);    // 1 per halfword with key16 <= T
            if (hitm) {
                int h = (hitm & 1) + (hitm >> 16);
                int pos = atomicAdd(&s_cnt[warp], h);
                int mi = mb + wi*2;
                if (hitm & 1)  { if (pos < CCAP) s_list[warp][pos] = (unsigned short)mi; ++pos; }
                if (hitm >> 16){ if (pos < CCAP) s_list[warp][pos] = (unsigned short)(mi + 1); }
            }
        }
    }
    __syncwarp();
    const int Q = min(s_cnt[warp], CCAP);

    // ---- recompute exact key32 per candidate (bit-identical chain to dist_gemm; q from smem) ----
    const float xxq = g_xx[b*NPTS + n];
    unsigned long long cand[6];
#pragma unroll
    for (int r = 0; r < 6; ++r) {
        cand[r] = 0ull;                       // 0 = empty sentinel (sorts to front)
        int idx = r*32 + lane;
        if (idx < Q) {
            int m = s_list[warp][idx];
            const float4* cp4 = (const float4*)(base + (size_t)(b*NPTS + m) * SP);
            const float4* qp4 = (const float4*)(s_q[warp]);
            float dot = 0.f;
#pragma unroll
            for (int c4 = 0; c4 < CP/4; ++c4) {
                float4 v = cp4[c4];
                float4 qv = qp4[c4];
                dot = fmaf(v.x, qv.x, dot);
                dot = fmaf(v.y, qv.y, dot);
                dot = fmaf(v.z, qv.z, dot);
                dot = fmaf(v.w, qv.w, dot);
            }
            float d = __fadd_rn(__fsub_rn(xxq, __fmul_rn(2.f, dot)), g_xx[b*NPTS + m]);
            cand[r] = ((unsigned long long)fkey(d) << 32) | (unsigned)m;
        }
    }
    // ascending sort-6 (Bose-Nelson); empties (0) first, lane max at cand[5]
    {
        unsigned long long t;
#define CE(a,bq) if (cand[a] > cand[bq]) { t = cand[a]; cand[a] = cand[bq]; cand[bq] = t; }
        CE(1,2) CE(4,5) CE(0,2) CE(3,5) CE(0,1) CE(3,4)
        CE(2,5) CE(0,3) CE(1,4) CE(2,4) CE(1,3) CE(2,3)
#undef CE
    }

    // ---- set-trim: pop the (Q-40) lex-LARGEST (key, m); survivors are exactly the top-40 set ----
    const int nPop = Q - KNN;
    for (int r = 0; r < nPop; ++r) {
        unsigned hi5 = (unsigned)(cand[5] >> 32);
        unsigned kmax = __reduce_max_sync(FULLM, hi5);
        bool tied = (hi5 == kmax);
        unsigned msel = __reduce_max_sync(FULLM, tied ? (unsigned)cand[5] : 0u);
        if (tied && (unsigned)cand[5] == msel) {
            cand[5] = cand[4]; cand[4] = cand[3]; cand[3] = cand[2];
            cand[2] = cand[1]; cand[1] = cand[0]; cand[0] = 0ull;
        }
    }
    // write surviving indices (order-free set)
#pragma unroll
    for (int r = 0; r < 6; ++r) {
        if (cand[r] != 0ull) {
            int p = atomicAdd(&s_ncnt[warp], 1);
            s_idx[warp*KNN + p] = (int)(unsigned)cand[r];
        }
    }
    __syncwarp();

    // ---- gather neighbor Z rows (128B coalesced), per-channel partials ----
    float S1 = 0.f, S2 = 0.f, Mx = -3.4028235e38f, Mn = 3.4028235e38f;
    const float* Zb = g_Z + (size_t)b * NPTS * 32;
#pragma unroll 5
    for (int k = 0; k < KNN; ++k) {
        int j = s_idx[warp*KNN + k];
        float z = Zb[(size_t)j*32 + lane];
        S1 += z;
        S2 = fmaf(z, z, S2);
        Mx = fmaxf(Mx, z);
        Mn = fminf(Mn, z);
    }
    const size_t pi = (size_t)(b*NPTS + n)*32 + lane;
    const float t = g_T[pi];
    g_Pmx[pi] = Mx + t;
    g_Pmn[pi] = Mn + t;
    double ssum = (double)S1 + (double)KNN * (double)t;
    double qsum = (double)S2 + 2.0*(double)t*(double)S1 + (double)KNN * (double)t * (double)t;

    s_red[warp*32 + lane]       = ssum;
    s_red[256 + warp*32 + lane] = qsum;
    __syncthreads();
    if (warp == 0) {
        double a = 0.0, c = 0.0;
#pragma unroll
        for (int w = 0; w < 8; ++w) { a += s_red[w*32 + lane]; c += s_red[256 + w*32 + lane]; }
        atomicAdd(&g_stats[lane],      a);
        atomicAdd(&g_stats[32 + lane], c);
    }
}

// ------------- final: pass-d(layer 4) fused + out = W5 (128x128) * cat -------------
__global__ void __launch_bounds__(128) final_fused(const float* __restrict__ W5,
                                                   const float* __restrict__ gamma,
                                                   const float* __restrict__ beta,
                                                   float* __restrict__ out)
{
    __shared__ float s[32*128];
    __shared__ float s_sc[32], s_sh[32];
    const int b = blockIdx.y, n0 = blockIdx.x * 32, t = threadIdx.x;

    // per-channel BN scale/shift (once per block)
    if (t < 32) {
        const double cnt = (double)B * (double)NPTS * (double)KNN;
        double meand = g_stats[t] / cnt;
        double vard  = g_stats[32 + t] / cnt - meand * meand;
        float inv  = rsqrtf((float)vard + 1e-5f);
        float sc = gamma[t] * inv;
        s_sc[t] = sc;
        s_sh[t] = beta[t] - (float)meand * sc;
    }

    // stage slices 0-2 (96 floats per point)
    for (int i = t; i < 32*24; i += 128) {
        int p = i / 24, c4 = i % 24;
        ((float4*)s)[p*32 + c4] =
            *(const float4*)(g_xcat + (size_t)(b*NPTS + n0 + p)*128 + c4*4);
    }
    __syncthreads();

    // compute slice 3 inline: pass-d(4) + residual from slice 2 (g_xcat slice-3 write is dead)
    for (int i = t; i < 32*32; i += 128) {
        int p = i >> 5, o = i & 31;
        float sc = s_sc[o], sh = s_sh[o];
        size_t pi = (size_t)(b*NPTS + n0 + p)*32 + o;
        float pre = (sc >= 0.f) ? g_Pmx[pi] : g_Pmn[pi];
        float y = fmaf(pre, sc, sh);
        y = (y >= 0.f) ? y : 0.2f * y;
        y += s[p*128 + 64 + o];               // residual x3
        s[p*128 + 96 + o] = y;
    }
    __syncthreads();

    float acc[32];
#pragma unroll
    for (int n = 0; n < 32; ++n) acc[n] = 0.f;
    const float4* Wrow = (const float4*)(W5 + (size_t)t * 128);
#pragma unroll 8
    for (int c4 = 0; c4 < 32; ++c4) {
        float4 w = __ldg(Wrow + c4);
#pragma unroll
        for (int n = 0; n < 32; ++n) {
            float4 xv = ((const float4*)s)[n*32 + c4];
            acc[n] = fmaf(w.x, xv.x, acc[n]);
            acc[n] = fmaf(w.y, xv.y, acc[n]);
            acc[n] = fmaf(w.z, xv.z, acc[n]);
            acc[n] = fmaf(w.w, xv.w, acc[n]);
        }
    }
    __syncthreads();
#pragma unroll
    for (int n = 0; n < 32; ++n) s[t*32 + n] = acc[n];
    __syncthreads();
    for (int i = t; i < 128*32; i += 128) {
        int o = i >> 5, n = i & 31;
        out[(size_t)(b*128 + o)*NPTS + n0 + n] = s[o*32 + n];
    }
}

// ------------------------------- host -------------------------------
extern "C" void kernel_launch(void* const* d_in, const int* in_sizes, int n_in,
                              void* d_out, int out_size)
{
    const float* x  = (const float*)d_in[0];
    const float* W1 = (const float*)d_in[1];
    const float* W2 = (const float*)d_in[2];
    const float* W3 = (const float*)d_in[3];
    const float* W4 = (const float*)d_in[4];
    const float* W5 = (const float*)d_in[5];
    const float* g1 = (const float*)d_in[6],  *b1 = (const float*)d_in[7];
    const float* g2 = (const float*)d_in[8],  *b2 = (const float*)d_in[9];
    const float* g3 = (const float*)d_in[10], *b3 = (const float*)d_in[11];
    const float* g4 = (const float*)d_in[12], *b4 = (const float*)d_in[13];
    float* out = (float*)d_out;

    dim3 g8(NPTS/8, B);
    dim3 gT(NPTS/256, B);
    dim3 gG(NPTS/128, NPTS/128, B);

    transpose_pad<<<gT, 256>>>(x);

    // layer 1 (input: padded x, C=9 (pad 12), SP=12)
    zt_first<<<g8, 256>>>(W1);
    dist_gemm<12><<<gG, 256>>>(0, 0, 12);
    knn_sel<12><<<g8, 256>>>(0, 0, 12);

    // layer 2 (pass_d(1) fused; input: x1 = slice 0)
    zt_fused<<<g8, 256>>>(1, g1, b1, W2);
    dist_gemm<32><<<gG, 256>>>(1, 0, 128);
    knn_sel<32><<<g8, 256>>>(1, 0, 128);

    // layer 3
    zt_fused<<<g8, 256>>>(2, g2, b2, W3);
    dist_gemm<32><<<gG, 256>>>(1, 32, 128);
    knn_sel<32><<<g8, 256>>>(1, 32, 128);

    // layer 4
    zt_fused<<<g8, 256>>>(3, g3, b3, W4);
    dist_gemm<32><<<gG, 256>>>(1, 64, 128);
    knn_sel<32><<<g8, 256>>>(1, 64, 128);

    // layer-4 pass-d fused into the final GEMM
    final_fused<<<dim3(NPTS/32, B), 128>>>(W5, g4, b4, out);
}